// round 13
// baseline (speedup 1.0000x reference)
#include <cuda_runtime.h>
#include <cuda_bf16.h>
#include <cuda_fp16.h>
#include <cstdint>

#define B_      512
#define GFS_    512
#define NATOMS_ 128
#define KATT_   256
#define NUNITS  (B_ * 2)

// ---------------- scratch (no cudaMalloc allowed) ----------------
__device__ float g_mgate[B_ * KATT_];
__device__ float g_M0[B_ * GFS_];
__device__ float g_spart[NUNITS][2][NATOMS_];                // partial logits per k-half
__device__ unsigned g_ticket[NUNITS];                        // last-CTA-done tickets
__device__ __half g_w16[2][KATT_ * GFS_];                    // W fp16
__device__ __half g_X16[2][(size_t)B_ * GFS_ * NATOMS_];     // X fp16, [b][f][n]

// ---------------- helpers ----------------
__device__ __forceinline__ uint32_t smem_u32(const void* p) {
    uint32_t a;
    asm("{ .reg .u64 t; cvta.to.shared.u64 t, %1; cvt.u32.u64 %0, t; }" : "=r"(a) : "l"(p));
    return a;
}
__device__ __forceinline__ uint32_t sw128(uint32_t off) { return off ^ ((off >> 3) & 0x70); }

__device__ __forceinline__ void ldsm_x4(uint32_t* r, uint32_t addr) {
    asm volatile("ldmatrix.sync.aligned.m8n8.x4.shared.b16 {%0,%1,%2,%3}, [%4];"
                 : "=r"(r[0]), "=r"(r[1]), "=r"(r[2]), "=r"(r[3]) : "r"(addr));
}
__device__ __forceinline__ void ldsm_x4t(uint32_t* r, uint32_t addr) {
    asm volatile("ldmatrix.sync.aligned.m8n8.x4.trans.shared.b16 {%0,%1,%2,%3}, [%4];"
                 : "=r"(r[0]), "=r"(r[1]), "=r"(r[2]), "=r"(r[3]) : "r"(addr));
}
__device__ __forceinline__ void mma_f16(float* c, const uint32_t* a, const uint32_t* b) {
    asm volatile("mma.sync.aligned.m16n8k16.row.col.f32.f16.f16.f32 "
                 "{%0,%1,%2,%3}, {%4,%5,%6,%7}, {%8,%9}, {%0,%1,%2,%3};"
                 : "+f"(c[0]), "+f"(c[1]), "+f"(c[2]), "+f"(c[3])
                 : "r"(a[0]), "r"(a[1]), "r"(a[2]), "r"(a[3]), "r"(b[0]), "r"(b[1]));
}
__device__ __forceinline__ void cp16(uint32_t saddr, const void* gaddr) {
    asm volatile("cp.async.cg.shared.global [%0], [%1], 16;" :: "r"(saddr), "l"(gaddr));
}
#define CP_COMMIT() asm volatile("cp.async.commit_group;" ::: "memory")
#define CP_WAIT0()  asm volatile("cp.async.wait_group 0;" ::: "memory")
#define CP_WAIT1()  asm volatile("cp.async.wait_group 1;" ::: "memory")
#define CP_WAIT2()  asm volatile("cp.async.wait_group 2;" ::: "memory")

// HW tanh (MUFU), rel err ~2^-11
__device__ __forceinline__ float htanh(float x) {
    float y;
    asm("tanh.approx.f32 %0, %1;" : "=f"(y) : "f"(x));
    return y;
}

// ---------------- precise rational tanh (gate path; |err| ~1e-7) ----------------
__device__ __forceinline__ float rtanh(float x) {
    float xc = fminf(fmaxf(x, -7.9053111f), 7.9053111f);
    float s = xc * xc;
    float p = -2.76076847742355e-16f;
    p = fmaf(p, s,  2.00018790482477e-13f);
    p = fmaf(p, s, -8.60467152213735e-11f);
    p = fmaf(p, s,  5.12229709037114e-08f);
    p = fmaf(p, s,  1.48572235717979e-05f);
    p = fmaf(p, s,  6.37261928875436e-04f);
    p = fmaf(p, s,  4.89352455891786e-03f);
    p = p * xc;
    float q = 1.19825839466702e-06f;
    q = fmaf(q, s, 1.18534705686654e-04f);
    q = fmaf(q, s, 2.26843463243900e-03f);
    q = fmaf(q, s, 4.89352518554385e-03f);
    return __fdividef(p, q);
}

// ---------------- P0: W -> fp16; reset tickets ----------------
__global__ __launch_bounds__(1024) void prep_kernel(const float* __restrict__ Wv,
                                                    const float* __restrict__ Wq)
{
    int id = blockIdx.x * 1024 + threadIdx.x;
    if (id < NUNITS) g_ticket[id] = 0u;
    int src = id >> 17;
    int e   = id & 131071;
    g_w16[src][e] = __float2half_rn((src ? Wq : Wv)[e]);
}

// ---------------- K1a: rowsums -> M0; X fp16 copy (16B stores) ----------------
__global__ __launch_bounds__(256) void m0_kernel(const float* __restrict__ V,
                                                 const float* __restrict__ Q)
{
    int b    = blockIdx.x >> 1;        // 1024 blocks
    int part = blockIdx.x & 1;         // 256 f each
    int lane = threadIdx.x & 31;
    int warp = threadIdx.x >> 5;       // 8 warps
    int half = lane >> 4;              // row select within pair
    int oct  = lane & 15;              // n-octet (8 n per lane)

    #pragma unroll 4
    for (int i = 0; i < 16; i++) {
        int f = part * 256 + warp * 32 + i * 2 + half;
        size_t base = ((size_t)b * GFS_ + f) * NATOMS_ + oct * 8;
        float4 v0 = __ldcs((const float4*)(V + base));
        float4 v1 = __ldcs((const float4*)(V + base + 4));
        float4 q0 = __ldcs((const float4*)(Q + base));
        float4 q1 = __ldcs((const float4*)(Q + base + 4));

        __half2 a0 = __floats2half2_rn(v0.x, v0.y);
        __half2 a1 = __floats2half2_rn(v0.z, v0.w);
        __half2 a2 = __floats2half2_rn(v1.x, v1.y);
        __half2 a3 = __floats2half2_rn(v1.z, v1.w);
        uint4 vu = { *(uint32_t*)&a0, *(uint32_t*)&a1, *(uint32_t*)&a2, *(uint32_t*)&a3 };
        __half2 c0 = __floats2half2_rn(q0.x, q0.y);
        __half2 c1 = __floats2half2_rn(q0.z, q0.w);
        __half2 c2 = __floats2half2_rn(q1.x, q1.y);
        __half2 c3 = __floats2half2_rn(q1.z, q1.w);
        uint4 qu = { *(uint32_t*)&c0, *(uint32_t*)&c1, *(uint32_t*)&c2, *(uint32_t*)&c3 };
        __stcs((uint4*)&g_X16[0][base], vu);
        __stcs((uint4*)&g_X16[1][base], qu);

        float sv = v0.x + v0.y + v0.z + v0.w + v1.x + v1.y + v1.z + v1.w;
        float sq = q0.x + q0.y + q0.z + q0.w + q1.x + q1.y + q1.z + q1.w;
        #pragma unroll
        for (int off = 8; off; off >>= 1) {   // reduce within 16-lane half
            sv += __shfl_xor_sync(0xffffffffu, sv, off);
            sq += __shfl_xor_sync(0xffffffffu, sq, off);
        }
        if (oct == 0)
            g_M0[b * GFS_ + f] = rtanh(sv * (1.0f / 64.0f)) * rtanh(sq * (1.0f / 64.0f));
    }
}

// ---------------- K1b: m_gate = tanh(Wm @ M0), 4 batches per CTA ----------------
__global__ __launch_bounds__(256) void gate_kernel(const float* __restrict__ Wm)
{
    __shared__ __align__(16) float M0s[4][GFS_];
    int b0  = blockIdx.x * 4;
    int tid = threadIdx.x;

    for (int i = tid; i < 4 * GFS_ / 4; i += 256)
        ((float4*)&M0s[0][0])[i] = ((const float4*)(g_M0 + b0 * GFS_))[i];
    __syncthreads();

    int k = tid;
    const float4* wr = (const float4*)(Wm + (size_t)k * GFS_);
    float acc0 = 0.f, acc1 = 0.f, acc2 = 0.f, acc3 = 0.f;
    #pragma unroll 4
    for (int i = 0; i < GFS_ / 4; i++) {
        float4 w = wr[i];
        float4 m0 = ((const float4*)M0s[0])[i];
        float4 m1 = ((const float4*)M0s[1])[i];
        float4 m2 = ((const float4*)M0s[2])[i];
        float4 m3 = ((const float4*)M0s[3])[i];
        acc0 = fmaf(w.x, m0.x, fmaf(w.y, m0.y, fmaf(w.z, m0.z, fmaf(w.w, m0.w, acc0))));
        acc1 = fmaf(w.x, m1.x, fmaf(w.y, m1.y, fmaf(w.z, m1.z, fmaf(w.w, m1.w, acc1))));
        acc2 = fmaf(w.x, m2.x, fmaf(w.y, m2.y, fmaf(w.z, m2.z, fmaf(w.w, m2.w, acc2))));
        acc3 = fmaf(w.x, m3.x, fmaf(w.y, m3.y, fmaf(w.z, m3.z, fmaf(w.w, m3.w, acc3))));
    }
    g_mgate[(b0 + 0) * KATT_ + k] = rtanh(acc0);
    g_mgate[(b0 + 1) * KATT_ + k] = rtanh(acc1);
    g_mgate[(b0 + 2) * KATT_ + k] = rtanh(acc2);
    g_mgate[(b0 + 3) * KATT_ + k] = rtanh(acc3);
}

// ---------------- K2: split-K GEMM + tanh-reduce + fused finish ----------------
#define A_OFF       0
#define B_OFFS      16384
#define STAGE_BYTES 32768
#define NSTAGE      3
#define WHG_OFF     98304
#define PART_OFF    98816
#define ALPHA_OFF   100864
#define FLAG_OFF    101376
#define SMEM_K2A    101504

// A chunk [128 m][64 f] fp16 SW128 (rows 128B)
__device__ __forceinline__ void fillA(uint32_t stage, const __half* Wc)
{
    int tid = threadIdx.x;
    #pragma unroll
    for (int it = 0; it < 4; it++) {
        int idx = it * 256 + tid;          // 0..1023
        int m   = idx >> 3;
        int u   = idx & 7;
        cp16(stage + A_OFF + sw128((uint32_t)(m * 128 + u * 16)),
             Wc + (size_t)m * GFS_ + u * 8);
    }
}

// B chunk [64 k(f)][128 n] fp16, rows 256B, 16B-unit XOR by (k&7)
__device__ __forceinline__ void fillB(uint32_t stage, const __half* Xc)
{
    int tid = threadIdx.x;
    #pragma unroll
    for (int it = 0; it < 4; it++) {
        int idx = it * 256 + tid;          // 0..1023
        int k   = idx >> 4;
        int u   = idx & 15;
        cp16(stage + B_OFFS + (uint32_t)(k * 256 + ((u << 4) ^ ((k & 7) << 4))),
             Xc + (size_t)k * NATOMS_ + u * 8);
    }
}

__global__ void __launch_bounds__(256, 2)
gemm_kernel(const float* __restrict__ Wh, float* __restrict__ out)
{
    extern __shared__ char sm[];
    uint32_t sb = smem_u32(sm);

    int tid  = threadIdx.x;
    int wid  = tid >> 5;        // 0..7
    int lane = tid & 31;

    int unit  = blockIdx.x >> 1;
    int khalf = blockIdx.x & 1;
    int src   = unit & 1;
    int b     = unit >> 1;

    const __half* W16  = g_w16[src] + (size_t)khalf * 128 * GFS_;
    const __half* Xrow = g_X16[src] + (size_t)b * GFS_ * NATOMS_;

    float* whg   = (float*)(sm + WHG_OFF);    // 128 gated weights for this k-half
    float* part  = (float*)(sm + PART_OFF);   // 4 x 128
    float* alpha = (float*)(sm + ALPHA_OFF);

    if (tid < 128) {
        int k = khalf * 128 + tid;
        whg[tid] = Wh[k] * g_mgate[b * KATT_ + k];
    }

    // warp tile: 32m x 64n; warp grid 4(m) x 2(n)
    int wm = wid >> 1;
    int wn = wid & 1;

    uint32_t aRow = (uint32_t)((wm * 32 + (lane & 15)) * 128);
    uint32_t aCol = (uint32_t)((lane >> 4) * 16);
    int q = lane >> 3;
    int r = lane & 7;
    uint32_t bKpart = (uint32_t)((q & 1) * 8 + r);
    uint32_t bUpart = (uint32_t)(wn * 8 + (q >> 1));   // 16B-unit base (+ jj*2)

    uint32_t stg[NSTAGE] = { sb, sb + STAGE_BYTES, sb + 2 * STAGE_BYTES };

    // prologue: chunks 0,1,2
    fillA(stg[0], W16);       fillB(stg[0], Xrow);                          CP_COMMIT();
    fillA(stg[1], W16 + 64);  fillB(stg[1], Xrow + (size_t)64  * NATOMS_);  CP_COMMIT();
    fillA(stg[2], W16 + 128); fillB(stg[2], Xrow + (size_t)128 * NATOMS_);  CP_COMMIT();

    float acc[2][8][4];
    #pragma unroll
    for (int i = 0; i < 2; i++)
        #pragma unroll
        for (int j = 0; j < 8; j++)
            #pragma unroll
            for (int e = 0; e < 4; e++) acc[i][j][e] = 0.0f;

    #pragma unroll 1
    for (int lc = 0; lc < 8; lc++) {
        if (lc < 6) CP_WAIT2(); else if (lc == 6) CP_WAIT1(); else CP_WAIT0();
        __syncthreads();                     // chunk lc visible block-wide

        int s = lc % 3;
        uint32_t aB = stg[s] + A_OFF;
        uint32_t bB = stg[s] + B_OFFS;

        #pragma unroll
        for (int ks = 0; ks < 4; ks++) {
            uint32_t kOff = (uint32_t)(ks * 32);
            uint32_t a4[8], b4[16];
            #pragma unroll
            for (int i = 0; i < 2; i++)
                ldsm_x4(&a4[i * 4], aB + sw128(aRow + i * 2048 + kOff + aCol));
            uint32_t kRow = (uint32_t)(ks * 16) + bKpart;
            #pragma unroll
            for (int jj = 0; jj < 4; jj++) {
                uint32_t un = bUpart + jj * 2;
                ldsm_x4t(&b4[jj * 4], bB + kRow * 256 + ((un * 16) ^ ((kRow & 7) * 16)));
            }
            #pragma unroll
            for (int i = 0; i < 2; i++)
                #pragma unroll
                for (int j = 0; j < 8; j++)
                    mma_f16(acc[i][j], &a4[i * 4], &b4[j * 2]);
        }

        if (lc < 5) {
            __syncthreads();                 // WAR: all consumed stage lc%3
            int f0 = (lc + 3) * 64;
            fillA(stg[s], W16 + f0);
            fillB(stg[s], Xrow + (size_t)f0 * NATOMS_);
            CP_COMMIT();
        }
    }

    // ---- epilogue: partial logits over this k-half ----
    float p[8][2];
    #pragma unroll
    for (int j = 0; j < 8; j++) { p[j][0] = 0.f; p[j][1] = 0.f; }

    int m0r = wm * 32 + (lane >> 2);
    #pragma unroll
    for (int i = 0; i < 2; i++) {
        float w0 = whg[m0r + i * 16];
        float w1 = whg[m0r + i * 16 + 8];
        #pragma unroll
        for (int j = 0; j < 8; j++) {
            p[j][0] = fmaf(w0, htanh(acc[i][j][0]), p[j][0]);
            p[j][1] = fmaf(w0, htanh(acc[i][j][1]), p[j][1]);
            p[j][0] = fmaf(w1, htanh(acc[i][j][2]), p[j][0]);
            p[j][1] = fmaf(w1, htanh(acc[i][j][3]), p[j][1]);
        }
    }
    #pragma unroll
    for (int off = 4; off <= 16; off <<= 1)
        #pragma unroll
        for (int j = 0; j < 8; j++) {
            p[j][0] += __shfl_xor_sync(0xffffffffu, p[j][0], off);
            p[j][1] += __shfl_xor_sync(0xffffffffu, p[j][1], off);
        }
    if (lane < 4) {
        #pragma unroll
        for (int j = 0; j < 8; j++) {
            int col = wn * 64 + j * 8 + lane * 2;
            part[wm * 128 + col]     = p[j][0];
            part[wm * 128 + col + 1] = p[j][1];
        }
    }
    __syncthreads();

    if (tid < 128) {
        float s = part[tid] + part[128 + tid] + part[256 + tid] + part[384 + tid];
        g_spart[unit][khalf][tid] = s;
    }
    __syncthreads();

    // ---- fused finish: last CTA of the unit does softmax + vector ----
    if (tid == 0) {
        __threadfence();                               // release my spart
        unsigned o = atomicAdd(&g_ticket[unit], 1u);
        *(unsigned*)(sm + FLAG_OFF) = o;
    }
    __syncthreads();
    if (*(unsigned*)(sm + FLAG_OFF) == 0) return;      // first finisher exits
    __threadfence();                                   // acquire other's spart

    // 2-sync softmax (warp-redundant over 128 logits)
    {
        float s[4];
        #pragma unroll
        for (int k = 0; k < 4; k++) {
            int n = lane + 32 * k;
            s[k] = g_spart[unit][0][n] + g_spart[unit][1][n];
        }
        float mx = fmaxf(fmaxf(s[0], s[1]), fmaxf(s[2], s[3]));
        #pragma unroll
        for (int off = 16; off; off >>= 1)
            mx = fmaxf(mx, __shfl_xor_sync(0xffffffffu, mx, off));
        float e[4], sum = 0.f;
        #pragma unroll
        for (int k = 0; k < 4; k++) { e[k] = __expf(s[k] - mx); sum += e[k]; }
        #pragma unroll
        for (int off = 16; off; off >>= 1)
            sum += __shfl_xor_sync(0xffffffffu, sum, off);
        float rs = 1.0f / sum;
        if (wid == 0) {
            #pragma unroll
            for (int k = 0; k < 4; k++) {
                int n = lane + 32 * k;
                float a = e[k] * rs;
                alpha[n] = a;
                out[2 * B_ * GFS_ + src * B_ * NATOMS_ + b * NATOMS_ + n] = a;
            }
        }
    }
    __syncthreads();

    // vector[f] = sum_n alpha[n] * X16[f][n]  (L2-hot), 2 f per thread
    #pragma unroll
    for (int rep = 0; rep < 2; rep++) {
        int f = tid + rep * 256;
        const uint4* xr = (const uint4*)(Xrow + (size_t)f * NATOMS_);
        float a = 0.0f;
        #pragma unroll
        for (int i = 0; i < 16; i++) {
            uint4 uu = xr[i];
            const float* al = alpha + i * 8;
            float2 p0 = __half22float2(*(const __half2*)&uu.x);
            float2 p1 = __half22float2(*(const __half2*)&uu.y);
            float2 p2 = __half22float2(*(const __half2*)&uu.z);
            float2 p3 = __half22float2(*(const __half2*)&uu.w);
            a = fmaf(p0.x, al[0], a); a = fmaf(p0.y, al[1], a);
            a = fmaf(p1.x, al[2], a); a = fmaf(p1.y, al[3], a);
            a = fmaf(p2.x, al[4], a); a = fmaf(p2.y, al[5], a);
            a = fmaf(p3.x, al[6], a); a = fmaf(p3.y, al[7], a);
        }
        out[src * B_ * GFS_ + b * GFS_ + f] = a;
    }
}

// ---------------- launch ----------------
extern "C" void kernel_launch(void* const* d_in, const int* in_sizes, int n_in,
                              void* d_out, int out_size)
{
    const float* V  = (const float*)d_in[0];
    const float* Q  = (const float*)d_in[1];
    const float* Wm = (const float*)d_in[2];
    const float* Wv = (const float*)d_in[3];
    const float* Wq = (const float*)d_in[4];
    const float* Wh = (const float*)d_in[5];
    float* out = (float*)d_out;

    cudaFuncSetAttribute(gemm_kernel, cudaFuncAttributeMaxDynamicSharedMemorySize, SMEM_K2A);

    prep_kernel<<<256, 1024>>>(Wv, Wq);
    m0_kernel<<<B_ * 2, 256>>>(V, Q);
    gate_kernel<<<B_ / 4, 256>>>(Wm);
    gemm_kernel<<<NUNITS * 2, 256, SMEM_K2A>>>(Wh, out);
}

// round 14
// speedup vs baseline: 1.0249x; 1.0249x over previous
#include <cuda_runtime.h>
#include <cuda_bf16.h>
#include <cuda_fp16.h>
#include <cstdint>

#define B_      512
#define GFS_    512
#define NATOMS_ 128
#define KATT_   256
#define NUNITS  (B_ * 2)

// ---------------- scratch (no cudaMalloc allowed) ----------------
__device__ float g_mgate[B_ * KATT_];
__device__ float g_M0[B_ * GFS_];
__device__ float g_spart[NUNITS][2][NATOMS_];                // partial logits per k-half
__device__ __half g_w16[2][KATT_ * GFS_];                    // W fp16
__device__ __half g_X16[2][(size_t)B_ * GFS_ * NATOMS_];     // X fp16, [b][f][n]

// ---------------- helpers ----------------
__device__ __forceinline__ uint32_t smem_u32(const void* p) {
    uint32_t a;
    asm("{ .reg .u64 t; cvta.to.shared.u64 t, %1; cvt.u32.u64 %0, t; }" : "=r"(a) : "l"(p));
    return a;
}
__device__ __forceinline__ uint32_t sw128(uint32_t off) { return off ^ ((off >> 3) & 0x70); }

__device__ __forceinline__ void ldsm_x4(uint32_t* r, uint32_t addr) {
    asm volatile("ldmatrix.sync.aligned.m8n8.x4.shared.b16 {%0,%1,%2,%3}, [%4];"
                 : "=r"(r[0]), "=r"(r[1]), "=r"(r[2]), "=r"(r[3]) : "r"(addr));
}
__device__ __forceinline__ void ldsm_x4t(uint32_t* r, uint32_t addr) {
    asm volatile("ldmatrix.sync.aligned.m8n8.x4.trans.shared.b16 {%0,%1,%2,%3}, [%4];"
                 : "=r"(r[0]), "=r"(r[1]), "=r"(r[2]), "=r"(r[3]) : "r"(addr));
}
__device__ __forceinline__ void mma_f16(float* c, const uint32_t* a, const uint32_t* b) {
    asm volatile("mma.sync.aligned.m16n8k16.row.col.f32.f16.f16.f32 "
                 "{%0,%1,%2,%3}, {%4,%5,%6,%7}, {%8,%9}, {%0,%1,%2,%3};"
                 : "+f"(c[0]), "+f"(c[1]), "+f"(c[2]), "+f"(c[3])
                 : "r"(a[0]), "r"(a[1]), "r"(a[2]), "r"(a[3]), "r"(b[0]), "r"(b[1]));
}
__device__ __forceinline__ void cp16(uint32_t saddr, const void* gaddr) {
    asm volatile("cp.async.cg.shared.global [%0], [%1], 16;" :: "r"(saddr), "l"(gaddr));
}
#define CP_COMMIT() asm volatile("cp.async.commit_group;" ::: "memory")
#define CP_WAIT0()  asm volatile("cp.async.wait_group 0;" ::: "memory")
#define CP_WAIT1()  asm volatile("cp.async.wait_group 1;" ::: "memory")
#define CP_WAIT2()  asm volatile("cp.async.wait_group 2;" ::: "memory")

// HW tanh (MUFU), rel err ~2^-11
__device__ __forceinline__ float htanh(float x) {
    float y;
    asm("tanh.approx.f32 %0, %1;" : "=f"(y) : "f"(x));
    return y;
}

// ---------------- precise rational tanh (gate path; |err| ~1e-7) ----------------
__device__ __forceinline__ float rtanh(float x) {
    float xc = fminf(fmaxf(x, -7.9053111f), 7.9053111f);
    float s = xc * xc;
    float p = -2.76076847742355e-16f;
    p = fmaf(p, s,  2.00018790482477e-13f);
    p = fmaf(p, s, -8.60467152213735e-11f);
    p = fmaf(p, s,  5.12229709037114e-08f);
    p = fmaf(p, s,  1.48572235717979e-05f);
    p = fmaf(p, s,  6.37261928875436e-04f);
    p = fmaf(p, s,  4.89352455891786e-03f);
    p = p * xc;
    float q = 1.19825839466702e-06f;
    q = fmaf(q, s, 1.18534705686654e-04f);
    q = fmaf(q, s, 2.26843463243900e-03f);
    q = fmaf(q, s, 4.89352518554385e-03f);
    return __fdividef(p, q);
}

// ---------------- P0: W -> fp16 ----------------
__global__ __launch_bounds__(1024) void prep_kernel(const float* __restrict__ Wv,
                                                    const float* __restrict__ Wq)
{
    int id = blockIdx.x * 1024 + threadIdx.x;
    int src = id >> 17;
    int e   = id & 131071;
    g_w16[src][e] = __float2half_rn((src ? Wq : Wv)[e]);
}

// ---------------- K1a: rowsums -> M0; X fp16 copy (16B stores) ----------------
__global__ __launch_bounds__(256) void m0_kernel(const float* __restrict__ V,
                                                 const float* __restrict__ Q)
{
    int b    = blockIdx.x >> 1;        // 1024 blocks
    int part = blockIdx.x & 1;         // 256 f each
    int lane = threadIdx.x & 31;
    int warp = threadIdx.x >> 5;       // 8 warps
    int half = lane >> 4;              // row select within pair
    int oct  = lane & 15;              // n-octet (8 n per lane)

    #pragma unroll 4
    for (int i = 0; i < 16; i++) {
        int f = part * 256 + warp * 32 + i * 2 + half;
        size_t base = ((size_t)b * GFS_ + f) * NATOMS_ + oct * 8;
        float4 v0 = __ldcs((const float4*)(V + base));
        float4 v1 = __ldcs((const float4*)(V + base + 4));
        float4 q0 = __ldcs((const float4*)(Q + base));
        float4 q1 = __ldcs((const float4*)(Q + base + 4));

        __half2 a0 = __floats2half2_rn(v0.x, v0.y);
        __half2 a1 = __floats2half2_rn(v0.z, v0.w);
        __half2 a2 = __floats2half2_rn(v1.x, v1.y);
        __half2 a3 = __floats2half2_rn(v1.z, v1.w);
        uint4 vu = { *(uint32_t*)&a0, *(uint32_t*)&a1, *(uint32_t*)&a2, *(uint32_t*)&a3 };
        __half2 c0 = __floats2half2_rn(q0.x, q0.y);
        __half2 c1 = __floats2half2_rn(q0.z, q0.w);
        __half2 c2 = __floats2half2_rn(q1.x, q1.y);
        __half2 c3 = __floats2half2_rn(q1.z, q1.w);
        uint4 qu = { *(uint32_t*)&c0, *(uint32_t*)&c1, *(uint32_t*)&c2, *(uint32_t*)&c3 };
        __stcs((uint4*)&g_X16[0][base], vu);
        __stcs((uint4*)&g_X16[1][base], qu);

        float sv = v0.x + v0.y + v0.z + v0.w + v1.x + v1.y + v1.z + v1.w;
        float sq = q0.x + q0.y + q0.z + q0.w + q1.x + q1.y + q1.z + q1.w;
        #pragma unroll
        for (int off = 8; off; off >>= 1) {   // reduce within 16-lane half
            sv += __shfl_xor_sync(0xffffffffu, sv, off);
            sq += __shfl_xor_sync(0xffffffffu, sq, off);
        }
        if (oct == 0)
            g_M0[b * GFS_ + f] = rtanh(sv * (1.0f / 64.0f)) * rtanh(sq * (1.0f / 64.0f));
    }
}

// ---------------- K1b: m_gate = tanh(Wm @ M0), 4 batches per CTA ----------------
__global__ __launch_bounds__(256) void gate_kernel(const float* __restrict__ Wm)
{
    __shared__ __align__(16) float M0s[4][GFS_];
    int b0  = blockIdx.x * 4;
    int tid = threadIdx.x;

    for (int i = tid; i < 4 * GFS_ / 4; i += 256)
        ((float4*)&M0s[0][0])[i] = ((const float4*)(g_M0 + b0 * GFS_))[i];
    __syncthreads();

    int k = tid;
    const float4* wr = (const float4*)(Wm + (size_t)k * GFS_);
    float acc0 = 0.f, acc1 = 0.f, acc2 = 0.f, acc3 = 0.f;
    #pragma unroll 4
    for (int i = 0; i < GFS_ / 4; i++) {
        float4 w = wr[i];
        float4 m0 = ((const float4*)M0s[0])[i];
        float4 m1 = ((const float4*)M0s[1])[i];
        float4 m2 = ((const float4*)M0s[2])[i];
        float4 m3 = ((const float4*)M0s[3])[i];
        acc0 = fmaf(w.x, m0.x, fmaf(w.y, m0.y, fmaf(w.z, m0.z, fmaf(w.w, m0.w, acc0))));
        acc1 = fmaf(w.x, m1.x, fmaf(w.y, m1.y, fmaf(w.z, m1.z, fmaf(w.w, m1.w, acc1))));
        acc2 = fmaf(w.x, m2.x, fmaf(w.y, m2.y, fmaf(w.z, m2.z, fmaf(w.w, m2.w, acc2))));
        acc3 = fmaf(w.x, m3.x, fmaf(w.y, m3.y, fmaf(w.z, m3.z, fmaf(w.w, m3.w, acc3))));
    }
    g_mgate[(b0 + 0) * KATT_ + k] = rtanh(acc0);
    g_mgate[(b0 + 1) * KATT_ + k] = rtanh(acc1);
    g_mgate[(b0 + 2) * KATT_ + k] = rtanh(acc2);
    g_mgate[(b0 + 3) * KATT_ + k] = rtanh(acc3);
}

// ---------------- K2a: split-K GEMM + tanh-reduce, 2 CTAs/SM (R12-verified) ----------------
#define A_OFF       0
#define B_OFFS      16384
#define STAGE_BYTES 32768
#define NSTAGE      3
#define WHG_OFF     98304
#define PART_OFF    98816
#define SMEM_K2A    100864

// A chunk [128 m][64 f] fp16 SW128 (rows 128B)
__device__ __forceinline__ void fillA(uint32_t stage, const __half* Wc)
{
    int tid = threadIdx.x;
    #pragma unroll
    for (int it = 0; it < 4; it++) {
        int idx = it * 256 + tid;          // 0..1023
        int m   = idx >> 3;
        int u   = idx & 7;
        cp16(stage + A_OFF + sw128((uint32_t)(m * 128 + u * 16)),
             Wc + (size_t)m * GFS_ + u * 8);
    }
}

// B chunk [64 k(f)][128 n] fp16, rows 256B, 16B-unit XOR by (k&7)
__device__ __forceinline__ void fillB(uint32_t stage, const __half* Xc)
{
    int tid = threadIdx.x;
    #pragma unroll
    for (int it = 0; it < 4; it++) {
        int idx = it * 256 + tid;          // 0..1023
        int k   = idx >> 4;
        int u   = idx & 15;
        cp16(stage + B_OFFS + (uint32_t)(k * 256 + ((u << 4) ^ ((k & 7) << 4))),
             Xc + (size_t)k * NATOMS_ + u * 8);
    }
}

__global__ void __launch_bounds__(256, 2)
gemm_kernel(const float* __restrict__ Wh)
{
    extern __shared__ char sm[];
    uint32_t sb = smem_u32(sm);

    int tid  = threadIdx.x;
    int wid  = tid >> 5;        // 0..7
    int lane = tid & 31;

    int unit  = blockIdx.x >> 1;
    int khalf = blockIdx.x & 1;
    int src   = unit & 1;
    int b     = unit >> 1;

    const __half* W16  = g_w16[src] + (size_t)khalf * 128 * GFS_;
    const __half* Xrow = g_X16[src] + (size_t)b * GFS_ * NATOMS_;

    float* whg  = (float*)(sm + WHG_OFF);    // 128 gated weights for this k-half
    float* part = (float*)(sm + PART_OFF);   // 4 x 128

    if (tid < 128) {
        int k = khalf * 128 + tid;
        whg[tid] = Wh[k] * g_mgate[b * KATT_ + k];
    }

    // warp tile: 32m x 64n; warp grid 4(m) x 2(n)
    int wm = wid >> 1;
    int wn = wid & 1;

    uint32_t aRow = (uint32_t)((wm * 32 + (lane & 15)) * 128);
    uint32_t aCol = (uint32_t)((lane >> 4) * 16);
    int q = lane >> 3;
    int r = lane & 7;
    uint32_t bKpart = (uint32_t)((q & 1) * 8 + r);
    uint32_t bUpart = (uint32_t)(wn * 8 + (q >> 1));   // 16B-unit base (+ jj*2)

    uint32_t stg[NSTAGE] = { sb, sb + STAGE_BYTES, sb + 2 * STAGE_BYTES };

    // prologue: chunks 0,1,2
    fillA(stg[0], W16);       fillB(stg[0], Xrow);                          CP_COMMIT();
    fillA(stg[1], W16 + 64);  fillB(stg[1], Xrow + (size_t)64  * NATOMS_);  CP_COMMIT();
    fillA(stg[2], W16 + 128); fillB(stg[2], Xrow + (size_t)128 * NATOMS_);  CP_COMMIT();

    float acc[2][8][4];
    #pragma unroll
    for (int i = 0; i < 2; i++)
        #pragma unroll
        for (int j = 0; j < 8; j++)
            #pragma unroll
            for (int e = 0; e < 4; e++) acc[i][j][e] = 0.0f;

    #pragma unroll 1
    for (int lc = 0; lc < 8; lc++) {
        if (lc < 6) CP_WAIT2(); else if (lc == 6) CP_WAIT1(); else CP_WAIT0();
        __syncthreads();                     // chunk lc visible block-wide

        int s = lc % 3;
        uint32_t aB = stg[s] + A_OFF;
        uint32_t bB = stg[s] + B_OFFS;

        #pragma unroll
        for (int ks = 0; ks < 4; ks++) {
            uint32_t kOff = (uint32_t)(ks * 32);
            uint32_t a4[8], b4[16];
            #pragma unroll
            for (int i = 0; i < 2; i++)
                ldsm_x4(&a4[i * 4], aB + sw128(aRow + i * 2048 + kOff + aCol));
            uint32_t kRow = (uint32_t)(ks * 16) + bKpart;
            #pragma unroll
            for (int jj = 0; jj < 4; jj++) {
                uint32_t un = bUpart + jj * 2;
                ldsm_x4t(&b4[jj * 4], bB + kRow * 256 + ((un * 16) ^ ((kRow & 7) * 16)));
            }
            #pragma unroll
            for (int i = 0; i < 2; i++)
                #pragma unroll
                for (int j = 0; j < 8; j++)
                    mma_f16(acc[i][j], &a4[i * 4], &b4[j * 2]);
        }

        if (lc < 5) {
            __syncthreads();                 // WAR: all consumed stage lc%3
            int f0 = (lc + 3) * 64;
            fillA(stg[s], W16 + f0);
            fillB(stg[s], Xrow + (size_t)f0 * NATOMS_);
            CP_COMMIT();
        }
    }

    // ---- epilogue: partial logits over this k-half ----
    float p[8][2];
    #pragma unroll
    for (int j = 0; j < 8; j++) { p[j][0] = 0.f; p[j][1] = 0.f; }

    int m0r = wm * 32 + (lane >> 2);
    #pragma unroll
    for (int i = 0; i < 2; i++) {
        float w0 = whg[m0r + i * 16];
        float w1 = whg[m0r + i * 16 + 8];
        #pragma unroll
        for (int j = 0; j < 8; j++) {
            p[j][0] = fmaf(w0, htanh(acc[i][j][0]), p[j][0]);
            p[j][1] = fmaf(w0, htanh(acc[i][j][1]), p[j][1]);
            p[j][0] = fmaf(w1, htanh(acc[i][j][2]), p[j][0]);
            p[j][1] = fmaf(w1, htanh(acc[i][j][3]), p[j][1]);
        }
    }
    #pragma unroll
    for (int off = 4; off <= 16; off <<= 1)
        #pragma unroll
        for (int j = 0; j < 8; j++) {
            p[j][0] += __shfl_xor_sync(0xffffffffu, p[j][0], off);
            p[j][1] += __shfl_xor_sync(0xffffffffu, p[j][1], off);
        }
    if (lane < 4) {
        #pragma unroll
        for (int j = 0; j < 8; j++) {
            int col = wn * 64 + j * 8 + lane * 2;
            part[wm * 128 + col]     = p[j][0];
            part[wm * 128 + col + 1] = p[j][1];
        }
    }
    __syncthreads();

    if (tid < 128) {
        float s = part[tid] + part[128 + tid] + part[256 + tid] + part[384 + tid];
        g_spart[unit][khalf][tid] = s;
    }
}

// ---------------- K2b: combine halves, softmax, alpha + vector outputs ----------------
__global__ void __launch_bounds__(256)
finish_kernel(float* __restrict__ out)
{
    __shared__ __align__(16) float alpha[NATOMS_];

    int tid  = threadIdx.x;
    int wid  = tid >> 5;
    int lane = tid & 31;

    int u   = blockIdx.x;
    int src = u & 1;
    int b   = u >> 1;

    const __half* Xrow = g_X16[src] + (size_t)b * GFS_ * NATOMS_;

    // every warp redundantly reduces all 128 logits (no cross-warp tree)
    {
        float s[4];
        #pragma unroll
        for (int k = 0; k < 4; k++) {
            int n = lane + 32 * k;
            s[k] = g_spart[u][0][n] + g_spart[u][1][n];
        }
        float mx = fmaxf(fmaxf(s[0], s[1]), fmaxf(s[2], s[3]));
        #pragma unroll
        for (int off = 16; off; off >>= 1)
            mx = fmaxf(mx, __shfl_xor_sync(0xffffffffu, mx, off));
        float e[4], sum = 0.f;
        #pragma unroll
        for (int k = 0; k < 4; k++) { e[k] = __expf(s[k] - mx); sum += e[k]; }
        #pragma unroll
        for (int off = 16; off; off >>= 1)
            sum += __shfl_xor_sync(0xffffffffu, sum, off);
        float rs = 1.0f / sum;
        if (wid == 0) {
            #pragma unroll
            for (int k = 0; k < 4; k++) {
                int n = lane + 32 * k;
                float a = e[k] * rs;
                alpha[n] = a;
                out[2 * B_ * GFS_ + src * B_ * NATOMS_ + b * NATOMS_ + n] = a;
            }
        }
    }
    __syncthreads();

    // vector[f] = sum_n alpha[n] * X16[f][n], 2 f per thread
    #pragma unroll
    for (int rep = 0; rep < 2; rep++) {
        int f = tid + rep * 256;
        const uint4* xr = (const uint4*)(Xrow + (size_t)f * NATOMS_);
        float a = 0.0f;
        #pragma unroll
        for (int i = 0; i < 16; i++) {
            uint4 uu = xr[i];
            const float* al = alpha + i * 8;
            float2 p0 = __half22float2(*(const __half2*)&uu.x);
            float2 p1 = __half22float2(*(const __half2*)&uu.y);
            float2 p2 = __half22float2(*(const __half2*)&uu.z);
            float2 p3 = __half22float2(*(const __half2*)&uu.w);
            a = fmaf(p0.x, al[0], a); a = fmaf(p0.y, al[1], a);
            a = fmaf(p1.x, al[2], a); a = fmaf(p1.y, al[3], a);
            a = fmaf(p2.x, al[4], a); a = fmaf(p2.y, al[5], a);
            a = fmaf(p3.x, al[6], a); a = fmaf(p3.y, al[7], a);
        }
        out[src * B_ * GFS_ + b * GFS_ + f] = a;
    }
}

// ---------------- launch ----------------
extern "C" void kernel_launch(void* const* d_in, const int* in_sizes, int n_in,
                              void* d_out, int out_size)
{
    const float* V  = (const float*)d_in[0];
    const float* Q  = (const float*)d_in[1];
    const float* Wm = (const float*)d_in[2];
    const float* Wv = (const float*)d_in[3];
    const float* Wq = (const float*)d_in[4];
    const float* Wh = (const float*)d_in[5];
    float* out = (float*)d_out;

    cudaFuncSetAttribute(gemm_kernel, cudaFuncAttributeMaxDynamicSharedMemorySize, SMEM_K2A);

    prep_kernel<<<256, 1024>>>(Wv, Wq);
    m0_kernel<<<B_ * 2, 256>>>(V, Q);
    gate_kernel<<<B_ / 4, 256>>>(Wm);
    gemm_kernel<<<NUNITS * 2, 256, SMEM_K2A>>>(Wh);
    finish_kernel<<<NUNITS, 256>>>(out);
}

// round 15
// speedup vs baseline: 1.1018x; 1.0750x over previous
#include <cuda_runtime.h>
#include <cuda_bf16.h>
#include <cuda_fp16.h>
#include <cstdint>

#define B_      512
#define GFS_    512
#define NATOMS_ 128
#define KATT_   256
#define NUNITS  (B_ * 2)

// ---------------- scratch (no cudaMalloc allowed) ----------------
__device__ float g_mgate[B_ * KATT_];
__device__ float g_M0[B_ * GFS_];
__device__ float g_spart[NUNITS][2][NATOMS_];                // partial logits per k-half
__device__ __half g_w16[2][KATT_ * GFS_];                    // W fp16
__device__ __half g_X16[2][(size_t)B_ * GFS_ * NATOMS_];     // X fp16, [b][f][n]

// ---------------- helpers ----------------
__device__ __forceinline__ uint32_t smem_u32(const void* p) {
    uint32_t a;
    asm("{ .reg .u64 t; cvta.to.shared.u64 t, %1; cvt.u32.u64 %0, t; }" : "=r"(a) : "l"(p));
    return a;
}
__device__ __forceinline__ uint32_t sw128(uint32_t off) { return off ^ ((off >> 3) & 0x70); }

__device__ __forceinline__ void ldsm_x4(uint32_t* r, uint32_t addr) {
    asm volatile("ldmatrix.sync.aligned.m8n8.x4.shared.b16 {%0,%1,%2,%3}, [%4];"
                 : "=r"(r[0]), "=r"(r[1]), "=r"(r[2]), "=r"(r[3]) : "r"(addr));
}
__device__ __forceinline__ void ldsm_x4t(uint32_t* r, uint32_t addr) {
    asm volatile("ldmatrix.sync.aligned.m8n8.x4.trans.shared.b16 {%0,%1,%2,%3}, [%4];"
                 : "=r"(r[0]), "=r"(r[1]), "=r"(r[2]), "=r"(r[3]) : "r"(addr));
}
__device__ __forceinline__ void mma_f16(float* c, const uint32_t* a, const uint32_t* b) {
    asm volatile("mma.sync.aligned.m16n8k16.row.col.f32.f16.f16.f32 "
                 "{%0,%1,%2,%3}, {%4,%5,%6,%7}, {%8,%9}, {%0,%1,%2,%3};"
                 : "+f"(c[0]), "+f"(c[1]), "+f"(c[2]), "+f"(c[3])
                 : "r"(a[0]), "r"(a[1]), "r"(a[2]), "r"(a[3]), "r"(b[0]), "r"(b[1]));
}
__device__ __forceinline__ void cp16(uint32_t saddr, const void* gaddr) {
    asm volatile("cp.async.cg.shared.global [%0], [%1], 16;" :: "r"(saddr), "l"(gaddr));
}
#define CP_COMMIT() asm volatile("cp.async.commit_group;" ::: "memory")
#define CP_WAIT0()  asm volatile("cp.async.wait_group 0;" ::: "memory")
#define CP_WAIT1()  asm volatile("cp.async.wait_group 1;" ::: "memory")
#define CP_WAIT2()  asm volatile("cp.async.wait_group 2;" ::: "memory")

// HW tanh (MUFU), rel err ~2^-11
__device__ __forceinline__ float htanh(float x) {
    float y;
    asm("tanh.approx.f32 %0, %1;" : "=f"(y) : "f"(x));
    return y;
}

// ---------------- precise rational tanh (gate path; |err| ~1e-7) ----------------
__device__ __forceinline__ float rtanh(float x) {
    float xc = fminf(fmaxf(x, -7.9053111f), 7.9053111f);
    float s = xc * xc;
    float p = -2.76076847742355e-16f;
    p = fmaf(p, s,  2.00018790482477e-13f);
    p = fmaf(p, s, -8.60467152213735e-11f);
    p = fmaf(p, s,  5.12229709037114e-08f);
    p = fmaf(p, s,  1.48572235717979e-05f);
    p = fmaf(p, s,  6.37261928875436e-04f);
    p = fmaf(p, s,  4.89352455891786e-03f);
    p = p * xc;
    float q = 1.19825839466702e-06f;
    q = fmaf(q, s, 1.18534705686654e-04f);
    q = fmaf(q, s, 2.26843463243900e-03f);
    q = fmaf(q, s, 4.89352518554385e-03f);
    return __fdividef(p, q);
}

// ---------------- P0: W -> fp16 ----------------
__global__ __launch_bounds__(1024) void prep_kernel(const float* __restrict__ Wv,
                                                    const float* __restrict__ Wq)
{
    int id = blockIdx.x * 1024 + threadIdx.x;
    int src = id >> 17;
    int e   = id & 131071;
    g_w16[src][e] = __float2half_rn((src ? Wq : Wv)[e]);
}

// ---------------- K1a (R12 version): rowsums -> M0; X fp16 copy ----------------
__global__ __launch_bounds__(256) void m0_kernel(const float* __restrict__ V,
                                                 const float* __restrict__ Q)
{
    int b    = blockIdx.x >> 2;
    int part = blockIdx.x & 3;
    int lane = threadIdx.x & 31;
    int warp = threadIdx.x >> 5;

    for (int i = 0; i < 16; i++) {
        int f = part * 128 + warp * 16 + i;
        size_t base = ((size_t)b * GFS_ + f) * NATOMS_;
        float4 v = __ldcs((const float4*)(V + base + lane * 4));
        float4 q = __ldcs((const float4*)(Q + base + lane * 4));

        __half2 vh0 = __floats2half2_rn(v.x, v.y);
        __half2 vh1 = __floats2half2_rn(v.z, v.w);
        __half2 qh0 = __floats2half2_rn(q.x, q.y);
        __half2 qh1 = __floats2half2_rn(q.z, q.w);
        uint2 vu = { *(uint32_t*)&vh0, *(uint32_t*)&vh1 };
        uint2 qu = { *(uint32_t*)&qh0, *(uint32_t*)&qh1 };
        *(uint2*)(&g_X16[0][base + lane * 4]) = vu;
        *(uint2*)(&g_X16[1][base + lane * 4]) = qu;

        float sv = v.x + v.y + v.z + v.w;
        float sq = q.x + q.y + q.z + q.w;
        #pragma unroll
        for (int off = 16; off; off >>= 1) {
            sv += __shfl_xor_sync(0xffffffffu, sv, off);
            sq += __shfl_xor_sync(0xffffffffu, sq, off);
        }
        if (lane == 0)
            g_M0[b * GFS_ + f] = rtanh(sv * (1.0f / 64.0f)) * rtanh(sq * (1.0f / 64.0f));
    }
}

// ---------------- K1b: m_gate = tanh(Wm @ M0), 4 batches per CTA ----------------
__global__ __launch_bounds__(256) void gate_kernel(const float* __restrict__ Wm)
{
    __shared__ __align__(16) float M0s[4][GFS_];
    int b0  = blockIdx.x * 4;
    int tid = threadIdx.x;

    for (int i = tid; i < 4 * GFS_ / 4; i += 256)
        ((float4*)&M0s[0][0])[i] = ((const float4*)(g_M0 + b0 * GFS_))[i];
    __syncthreads();

    int k = tid;
    const float4* wr = (const float4*)(Wm + (size_t)k * GFS_);
    float acc0 = 0.f, acc1 = 0.f, acc2 = 0.f, acc3 = 0.f;
    #pragma unroll 4
    for (int i = 0; i < GFS_ / 4; i++) {
        float4 w = wr[i];
        float4 m0 = ((const float4*)M0s[0])[i];
        float4 m1 = ((const float4*)M0s[1])[i];
        float4 m2 = ((const float4*)M0s[2])[i];
        float4 m3 = ((const float4*)M0s[3])[i];
        acc0 = fmaf(w.x, m0.x, fmaf(w.y, m0.y, fmaf(w.z, m0.z, fmaf(w.w, m0.w, acc0))));
        acc1 = fmaf(w.x, m1.x, fmaf(w.y, m1.y, fmaf(w.z, m1.z, fmaf(w.w, m1.w, acc1))));
        acc2 = fmaf(w.x, m2.x, fmaf(w.y, m2.y, fmaf(w.z, m2.z, fmaf(w.w, m2.w, acc2))));
        acc3 = fmaf(w.x, m3.x, fmaf(w.y, m3.y, fmaf(w.z, m3.z, fmaf(w.w, m3.w, acc3))));
    }
    g_mgate[(b0 + 0) * KATT_ + k] = rtanh(acc0);
    g_mgate[(b0 + 1) * KATT_ + k] = rtanh(acc1);
    g_mgate[(b0 + 2) * KATT_ + k] = rtanh(acc2);
    g_mgate[(b0 + 3) * KATT_ + k] = rtanh(acc3);
}

// ---------------- K2a: split-K GEMM + tanh-reduce, 2 CTAs/SM (R12-verified) ----------------
#define A_OFF       0
#define B_OFFS      16384
#define STAGE_BYTES 32768
#define NSTAGE      3
#define WHG_OFF     98304
#define PART_OFF    98816
#define SMEM_K2A    100864

// A chunk [128 m][64 f] fp16 SW128 (rows 128B)
__device__ __forceinline__ void fillA(uint32_t stage, const __half* Wc)
{
    int tid = threadIdx.x;
    #pragma unroll
    for (int it = 0; it < 4; it++) {
        int idx = it * 256 + tid;          // 0..1023
        int m   = idx >> 3;
        int u   = idx & 7;
        cp16(stage + A_OFF + sw128((uint32_t)(m * 128 + u * 16)),
             Wc + (size_t)m * GFS_ + u * 8);
    }
}

// B chunk [64 k(f)][128 n] fp16, rows 256B, 16B-unit XOR by (k&7)
__device__ __forceinline__ void fillB(uint32_t stage, const __half* Xc)
{
    int tid = threadIdx.x;
    #pragma unroll
    for (int it = 0; it < 4; it++) {
        int idx = it * 256 + tid;          // 0..1023
        int k   = idx >> 4;
        int u   = idx & 15;
        cp16(stage + B_OFFS + (uint32_t)(k * 256 + ((u << 4) ^ ((k & 7) << 4))),
             Xc + (size_t)k * NATOMS_ + u * 8);
    }
}

__global__ void __launch_bounds__(256, 2)
gemm_kernel(const float* __restrict__ Wh)
{
    extern __shared__ char sm[];
    uint32_t sb = smem_u32(sm);

    int tid  = threadIdx.x;
    int wid  = tid >> 5;        // 0..7
    int lane = tid & 31;

    int unit  = blockIdx.x >> 1;
    int khalf = blockIdx.x & 1;
    int src   = unit & 1;
    int b     = unit >> 1;

    const __half* W16  = g_w16[src] + (size_t)khalf * 128 * GFS_;
    const __half* Xrow = g_X16[src] + (size_t)b * GFS_ * NATOMS_;

    float* whg  = (float*)(sm + WHG_OFF);    // 128 gated weights for this k-half
    float* part = (float*)(sm + PART_OFF);   // 4 x 128

    if (tid < 128) {
        int k = khalf * 128 + tid;
        whg[tid] = Wh[k] * g_mgate[b * KATT_ + k];
    }

    // warp tile: 32m x 64n; warp grid 4(m) x 2(n)
    int wm = wid >> 1;
    int wn = wid & 1;

    uint32_t aRow = (uint32_t)((wm * 32 + (lane & 15)) * 128);
    uint32_t aCol = (uint32_t)((lane >> 4) * 16);
    int q = lane >> 3;
    int r = lane & 7;
    uint32_t bKpart = (uint32_t)((q & 1) * 8 + r);
    uint32_t bUpart = (uint32_t)(wn * 8 + (q >> 1));   // 16B-unit base (+ jj*2)

    uint32_t stg[NSTAGE] = { sb, sb + STAGE_BYTES, sb + 2 * STAGE_BYTES };

    // prologue: chunks 0,1,2
    fillA(stg[0], W16);       fillB(stg[0], Xrow);                          CP_COMMIT();
    fillA(stg[1], W16 + 64);  fillB(stg[1], Xrow + (size_t)64  * NATOMS_);  CP_COMMIT();
    fillA(stg[2], W16 + 128); fillB(stg[2], Xrow + (size_t)128 * NATOMS_);  CP_COMMIT();

    float acc[2][8][4];
    #pragma unroll
    for (int i = 0; i < 2; i++)
        #pragma unroll
        for (int j = 0; j < 8; j++)
            #pragma unroll
            for (int e = 0; e < 4; e++) acc[i][j][e] = 0.0f;

    #pragma unroll 1
    for (int lc = 0; lc < 8; lc++) {
        if (lc < 6) CP_WAIT2(); else if (lc == 6) CP_WAIT1(); else CP_WAIT0();
        __syncthreads();                     // chunk lc visible block-wide

        int s = lc % 3;
        uint32_t aB = stg[s] + A_OFF;
        uint32_t bB = stg[s] + B_OFFS;

        #pragma unroll
        for (int ks = 0; ks < 4; ks++) {
            uint32_t kOff = (uint32_t)(ks * 32);
            uint32_t a4[8], b4[16];
            #pragma unroll
            for (int i = 0; i < 2; i++)
                ldsm_x4(&a4[i * 4], aB + sw128(aRow + i * 2048 + kOff + aCol));
            uint32_t kRow = (uint32_t)(ks * 16) + bKpart;
            #pragma unroll
            for (int jj = 0; jj < 4; jj++) {
                uint32_t un = bUpart + jj * 2;
                ldsm_x4t(&b4[jj * 4], bB + kRow * 256 + ((un * 16) ^ ((kRow & 7) * 16)));
            }
            #pragma unroll
            for (int i = 0; i < 2; i++)
                #pragma unroll
                for (int j = 0; j < 8; j++)
                    mma_f16(acc[i][j], &a4[i * 4], &b4[j * 2]);
        }

        if (lc < 5) {
            __syncthreads();                 // WAR: all consumed stage lc%3
            int f0 = (lc + 3) * 64;
            fillA(stg[s], W16 + f0);
            fillB(stg[s], Xrow + (size_t)f0 * NATOMS_);
            CP_COMMIT();
        }
    }

    // ---- epilogue: partial logits over this k-half ----
    float p[8][2];
    #pragma unroll
    for (int j = 0; j < 8; j++) { p[j][0] = 0.f; p[j][1] = 0.f; }

    int m0r = wm * 32 + (lane >> 2);
    #pragma unroll
    for (int i = 0; i < 2; i++) {
        float w0 = whg[m0r + i * 16];
        float w1 = whg[m0r + i * 16 + 8];
        #pragma unroll
        for (int j = 0; j < 8; j++) {
            p[j][0] = fmaf(w0, htanh(acc[i][j][0]), p[j][0]);
            p[j][1] = fmaf(w0, htanh(acc[i][j][1]), p[j][1]);
            p[j][0] = fmaf(w1, htanh(acc[i][j][2]), p[j][0]);
            p[j][1] = fmaf(w1, htanh(acc[i][j][3]), p[j][1]);
        }
    }
    #pragma unroll
    for (int off = 4; off <= 16; off <<= 1)
        #pragma unroll
        for (int j = 0; j < 8; j++) {
            p[j][0] += __shfl_xor_sync(0xffffffffu, p[j][0], off);
            p[j][1] += __shfl_xor_sync(0xffffffffu, p[j][1], off);
        }
    if (lane < 4) {
        #pragma unroll
        for (int j = 0; j < 8; j++) {
            int col = wn * 64 + j * 8 + lane * 2;
            part[wm * 128 + col]     = p[j][0];
            part[wm * 128 + col + 1] = p[j][1];
        }
    }
    __syncthreads();

    if (tid < 128) {
        float s = part[tid] + part[128 + tid] + part[256 + tid] + part[384 + tid];
        g_spart[unit][khalf][tid] = s;
    }
}

// ---------------- K2b: combine halves, softmax, alpha + vector outputs ----------------
// Reverse unit order: first-scheduled finish CTAs hit gemm's last (L2-hot) units.
__global__ void __launch_bounds__(512)
finish_kernel(float* __restrict__ out)
{
    __shared__ __align__(16) float alpha[NATOMS_];

    int tid  = threadIdx.x;
    int wid  = tid >> 5;
    int lane = tid & 31;

    int u   = (NUNITS - 1) - blockIdx.x;
    int src = u & 1;
    int b   = u >> 1;

    const __half* Xrow = g_X16[src] + (size_t)b * GFS_ * NATOMS_;

    // every warp redundantly reduces all 128 logits (no cross-warp tree)
    {
        float s[4];
        #pragma unroll
        for (int k = 0; k < 4; k++) {
            int n = lane + 32 * k;
            s[k] = g_spart[u][0][n] + g_spart[u][1][n];
        }
        float mx = fmaxf(fmaxf(s[0], s[1]), fmaxf(s[2], s[3]));
        #pragma unroll
        for (int off = 16; off; off >>= 1)
            mx = fmaxf(mx, __shfl_xor_sync(0xffffffffu, mx, off));
        float e[4], sum = 0.f;
        #pragma unroll
        for (int k = 0; k < 4; k++) { e[k] = __expf(s[k] - mx); sum += e[k]; }
        #pragma unroll
        for (int off = 16; off; off >>= 1)
            sum += __shfl_xor_sync(0xffffffffu, sum, off);
        float rs = 1.0f / sum;
        if (wid == 0) {
            #pragma unroll
            for (int k = 0; k < 4; k++) {
                int n = lane + 32 * k;
                float a = e[k] * rs;
                alpha[n] = a;
                out[2 * B_ * GFS_ + src * B_ * NATOMS_ + b * NATOMS_ + n] = a;
            }
        }
    }
    __syncthreads();

    // vector[f] = sum_n alpha[n] * X16[f][n], 1 f per thread (512 threads)
    {
        int f = tid;
        const uint4* xr = (const uint4*)(Xrow + (size_t)f * NATOMS_);
        float a = 0.0f;
        #pragma unroll
        for (int i = 0; i < 16; i++) {
            uint4 uu = xr[i];
            const float* al = alpha + i * 8;
            float2 p0 = __half22float2(*(const __half2*)&uu.x);
            float2 p1 = __half22float2(*(const __half2*)&uu.y);
            float2 p2 = __half22float2(*(const __half2*)&uu.z);
            float2 p3 = __half22float2(*(const __half2*)&uu.w);
            a = fmaf(p0.x, al[0], a); a = fmaf(p0.y, al[1], a);
            a = fmaf(p1.x, al[2], a); a = fmaf(p1.y, al[3], a);
            a = fmaf(p2.x, al[4], a); a = fmaf(p2.y, al[5], a);
            a = fmaf(p3.x, al[6], a); a = fmaf(p3.y, al[7], a);
        }
        out[src * B_ * GFS_ + b * GFS_ + f] = a;
    }
}

// ---------------- launch ----------------
extern "C" void kernel_launch(void* const* d_in, const int* in_sizes, int n_in,
                              void* d_out, int out_size)
{
    const float* V  = (const float*)d_in[0];
    const float* Q  = (const float*)d_in[1];
    const float* Wm = (const float*)d_in[2];
    const float* Wv = (const float*)d_in[3];
    const float* Wq = (const float*)d_in[4];
    const float* Wh = (const float*)d_in[5];
    float* out = (float*)d_out;

    cudaFuncSetAttribute(gemm_kernel, cudaFuncAttributeMaxDynamicSharedMemorySize, SMEM_K2A);

    prep_kernel<<<256, 1024>>>(Wv, Wq);
    m0_kernel<<<B_ * 4, 256>>>(V, Q);
    gate_kernel<<<B_ / 4, 256>>>(Wm);
    gemm_kernel<<<NUNITS * 2, 256, SMEM_K2A>>>(Wh);
    finish_kernel<<<NUNITS, 512>>>(out);
}

// round 16
// speedup vs baseline: 1.1231x; 1.0194x over previous
#include <cuda_runtime.h>
#include <cuda_bf16.h>
#include <cuda_fp16.h>
#include <cstdint>

#define B_      512
#define GFS_    512
#define NATOMS_ 128
#define KATT_   256
#define NUNITS  (B_ * 2)

// ---------------- scratch (no cudaMalloc allowed) ----------------
__device__ float g_mgate[B_ * KATT_];
__device__ float g_M0[B_ * GFS_];
__device__ float g_spart[NUNITS][2][NATOMS_];                // partial logits per k-half
__device__ __half g_w16[2][KATT_ * GFS_];                    // W fp16
__device__ __half g_X16[2][(size_t)B_ * GFS_ * NATOMS_];     // X fp16, [b][f][n]

// ---------------- helpers ----------------
__device__ __forceinline__ uint32_t smem_u32(const void* p) {
    uint32_t a;
    asm("{ .reg .u64 t; cvta.to.shared.u64 t, %1; cvt.u32.u64 %0, t; }" : "=r"(a) : "l"(p));
    return a;
}
__device__ __forceinline__ uint32_t sw128(uint32_t off) { return off ^ ((off >> 3) & 0x70); }

__device__ __forceinline__ void ldsm_x4(uint32_t* r, uint32_t addr) {
    asm volatile("ldmatrix.sync.aligned.m8n8.x4.shared.b16 {%0,%1,%2,%3}, [%4];"
                 : "=r"(r[0]), "=r"(r[1]), "=r"(r[2]), "=r"(r[3]) : "r"(addr));
}
__device__ __forceinline__ void ldsm_x4t(uint32_t* r, uint32_t addr) {
    asm volatile("ldmatrix.sync.aligned.m8n8.x4.trans.shared.b16 {%0,%1,%2,%3}, [%4];"
                 : "=r"(r[0]), "=r"(r[1]), "=r"(r[2]), "=r"(r[3]) : "r"(addr));
}
__device__ __forceinline__ void mma_f16(float* c, const uint32_t* a, const uint32_t* b) {
    asm volatile("mma.sync.aligned.m16n8k16.row.col.f32.f16.f16.f32 "
                 "{%0,%1,%2,%3}, {%4,%5,%6,%7}, {%8,%9}, {%0,%1,%2,%3};"
                 : "+f"(c[0]), "+f"(c[1]), "+f"(c[2]), "+f"(c[3])
                 : "r"(a[0]), "r"(a[1]), "r"(a[2]), "r"(a[3]), "r"(b[0]), "r"(b[1]));
}
__device__ __forceinline__ void cp16(uint32_t saddr, const void* gaddr) {
    asm volatile("cp.async.cg.shared.global [%0], [%1], 16;" :: "r"(saddr), "l"(gaddr));
}
#define CP_COMMIT() asm volatile("cp.async.commit_group;" ::: "memory")
#define CP_WAIT0()  asm volatile("cp.async.wait_group 0;" ::: "memory")
#define CP_WAIT1()  asm volatile("cp.async.wait_group 1;" ::: "memory")
#define CP_WAIT2()  asm volatile("cp.async.wait_group 2;" ::: "memory")

// HW tanh (MUFU), rel err ~2^-11
__device__ __forceinline__ float htanh(float x) {
    float y;
    asm("tanh.approx.f32 %0, %1;" : "=f"(y) : "f"(x));
    return y;
}

// ---------------- precise rational tanh (gate path; |err| ~1e-7) ----------------
__device__ __forceinline__ float rtanh(float x) {
    float xc = fminf(fmaxf(x, -7.9053111f), 7.9053111f);
    float s = xc * xc;
    float p = -2.76076847742355e-16f;
    p = fmaf(p, s,  2.00018790482477e-13f);
    p = fmaf(p, s, -8.60467152213735e-11f);
    p = fmaf(p, s,  5.12229709037114e-08f);
    p = fmaf(p, s,  1.48572235717979e-05f);
    p = fmaf(p, s,  6.37261928875436e-04f);
    p = fmaf(p, s,  4.89352455891786e-03f);
    p = p * xc;
    float q = 1.19825839466702e-06f;
    q = fmaf(q, s, 1.18534705686654e-04f);
    q = fmaf(q, s, 2.26843463243900e-03f);
    q = fmaf(q, s, 4.89352518554385e-03f);
    return __fdividef(p, q);
}

// ---------------- K1a: rowsums -> M0 + X fp16 copy + (folded) W -> fp16 ----------------
// blocks [0, 2048): m0/X16 work. blocks [2048, 2304): W conversion (old prep).
__global__ __launch_bounds__(256) void m0_kernel(const float* __restrict__ V,
                                                 const float* __restrict__ Q,
                                                 const float* __restrict__ Wv,
                                                 const float* __restrict__ Wq)
{
    if (blockIdx.x >= 2048) {
        // ---- W conversion: 256 blocks x 256 threads x 4 elems ----
        int id  = (blockIdx.x - 2048) * 256 + threadIdx.x;   // 0..65535
        int src = id >> 15;
        int e   = (id & 32767) * 4;
        const float* W = src ? Wq : Wv;
        float4 w = *(const float4*)(W + e);
        __half2 h0 = __floats2half2_rn(w.x, w.y);
        __half2 h1 = __floats2half2_rn(w.z, w.w);
        uint2 u = { *(uint32_t*)&h0, *(uint32_t*)&h1 };
        *(uint2*)(&g_w16[src][e]) = u;
        return;
    }

    int b    = blockIdx.x >> 2;
    int part = blockIdx.x & 3;
    int lane = threadIdx.x & 31;
    int warp = threadIdx.x >> 5;

    #pragma unroll
    for (int g = 0; g < 4; g++) {
        int f0 = part * 128 + warp * 16 + g * 4;
        size_t base = ((size_t)b * GFS_ + f0) * NATOMS_ + lane * 4;

        // batch all 8 loads (MLP=8) before any dependent work
        float4 v[4], q[4];
        #pragma unroll
        for (int j = 0; j < 4; j++) {
            v[j] = __ldcs((const float4*)(V + base + (size_t)j * NATOMS_));
            q[j] = __ldcs((const float4*)(Q + base + (size_t)j * NATOMS_));
        }

        // convert + store fp16 copies
        #pragma unroll
        for (int j = 0; j < 4; j++) {
            __half2 vh0 = __floats2half2_rn(v[j].x, v[j].y);
            __half2 vh1 = __floats2half2_rn(v[j].z, v[j].w);
            __half2 qh0 = __floats2half2_rn(q[j].x, q[j].y);
            __half2 qh1 = __floats2half2_rn(q[j].z, q[j].w);
            uint2 vu = { *(uint32_t*)&vh0, *(uint32_t*)&vh1 };
            uint2 qu = { *(uint32_t*)&qh0, *(uint32_t*)&qh1 };
            __stcs((uint2*)(&g_X16[0][base + (size_t)j * NATOMS_]), vu);
            __stcs((uint2*)(&g_X16[1][base + (size_t)j * NATOMS_]), qu);
        }

        // rowsum reduce (same order as R12/R15 -> bit-identical)
        #pragma unroll
        for (int j = 0; j < 4; j++) {
            float sv = v[j].x + v[j].y + v[j].z + v[j].w;
            float sq = q[j].x + q[j].y + q[j].z + q[j].w;
            #pragma unroll
            for (int off = 16; off; off >>= 1) {
                sv += __shfl_xor_sync(0xffffffffu, sv, off);
                sq += __shfl_xor_sync(0xffffffffu, sq, off);
            }
            if (lane == 0)
                g_M0[b * GFS_ + f0 + j] = rtanh(sv * (1.0f / 64.0f)) * rtanh(sq * (1.0f / 64.0f));
        }
    }
}

// ---------------- K1b: m_gate = tanh(Wm @ M0), 4 batches per CTA ----------------
__global__ __launch_bounds__(256) void gate_kernel(const float* __restrict__ Wm)
{
    __shared__ __align__(16) float M0s[4][GFS_];
    int b0  = blockIdx.x * 4;
    int tid = threadIdx.x;

    for (int i = tid; i < 4 * GFS_ / 4; i += 256)
        ((float4*)&M0s[0][0])[i] = ((const float4*)(g_M0 + b0 * GFS_))[i];
    __syncthreads();

    int k = tid;
    const float4* wr = (const float4*)(Wm + (size_t)k * GFS_);
    float acc0 = 0.f, acc1 = 0.f, acc2 = 0.f, acc3 = 0.f;
    #pragma unroll 4
    for (int i = 0; i < GFS_ / 4; i++) {
        float4 w = wr[i];
        float4 m0 = ((const float4*)M0s[0])[i];
        float4 m1 = ((const float4*)M0s[1])[i];
        float4 m2 = ((const float4*)M0s[2])[i];
        float4 m3 = ((const float4*)M0s[3])[i];
        acc0 = fmaf(w.x, m0.x, fmaf(w.y, m0.y, fmaf(w.z, m0.z, fmaf(w.w, m0.w, acc0))));
        acc1 = fmaf(w.x, m1.x, fmaf(w.y, m1.y, fmaf(w.z, m1.z, fmaf(w.w, m1.w, acc1))));
        acc2 = fmaf(w.x, m2.x, fmaf(w.y, m2.y, fmaf(w.z, m2.z, fmaf(w.w, m2.w, acc2))));
        acc3 = fmaf(w.x, m3.x, fmaf(w.y, m3.y, fmaf(w.z, m3.z, fmaf(w.w, m3.w, acc3))));
    }
    g_mgate[(b0 + 0) * KATT_ + k] = rtanh(acc0);
    g_mgate[(b0 + 1) * KATT_ + k] = rtanh(acc1);
    g_mgate[(b0 + 2) * KATT_ + k] = rtanh(acc2);
    g_mgate[(b0 + 3) * KATT_ + k] = rtanh(acc3);
}

// ---------------- K2a: split-K GEMM + tanh-reduce, 2 CTAs/SM (R12-verified) ----------------
#define A_OFF       0
#define B_OFFS      16384
#define STAGE_BYTES 32768
#define NSTAGE      3
#define WHG_OFF     98304
#define PART_OFF    98816
#define SMEM_K2A    100864

// A chunk [128 m][64 f] fp16 SW128 (rows 128B)
__device__ __forceinline__ void fillA(uint32_t stage, const __half* Wc)
{
    int tid = threadIdx.x;
    #pragma unroll
    for (int it = 0; it < 4; it++) {
        int idx = it * 256 + tid;          // 0..1023
        int m   = idx >> 3;
        int u   = idx & 7;
        cp16(stage + A_OFF + sw128((uint32_t)(m * 128 + u * 16)),
             Wc + (size_t)m * GFS_ + u * 8);
    }
}

// B chunk [64 k(f)][128 n] fp16, rows 256B, 16B-unit XOR by (k&7)
__device__ __forceinline__ void fillB(uint32_t stage, const __half* Xc)
{
    int tid = threadIdx.x;
    #pragma unroll
    for (int it = 0; it < 4; it++) {
        int idx = it * 256 + tid;          // 0..1023
        int k   = idx >> 4;
        int u   = idx & 15;
        cp16(stage + B_OFFS + (uint32_t)(k * 256 + ((u << 4) ^ ((k & 7) << 4))),
             Xc + (size_t)k * NATOMS_ + u * 8);
    }
}

__global__ void __launch_bounds__(256, 2)
gemm_kernel(const float* __restrict__ Wh)
{
    extern __shared__ char sm[];
    uint32_t sb = smem_u32(sm);

    int tid  = threadIdx.x;
    int wid  = tid >> 5;        // 0..7
    int lane = tid & 31;

    int unit  = blockIdx.x >> 1;
    int khalf = blockIdx.x & 1;
    int src   = unit & 1;
    int b     = unit >> 1;

    const __half* W16  = g_w16[src] + (size_t)khalf * 128 * GFS_;
    const __half* Xrow = g_X16[src] + (size_t)b * GFS_ * NATOMS_;

    float* whg  = (float*)(sm + WHG_OFF);    // 128 gated weights for this k-half
    float* part = (float*)(sm + PART_OFF);   // 4 x 128

    if (tid < 128) {
        int k = khalf * 128 + tid;
        whg[tid] = Wh[k] * g_mgate[b * KATT_ + k];
    }

    // warp tile: 32m x 64n; warp grid 4(m) x 2(n)
    int wm = wid >> 1;
    int wn = wid & 1;

    uint32_t aRow = (uint32_t)((wm * 32 + (lane & 15)) * 128);
    uint32_t aCol = (uint32_t)((lane >> 4) * 16);
    int q = lane >> 3;
    int r = lane & 7;
    uint32_t bKpart = (uint32_t)((q & 1) * 8 + r);
    uint32_t bUpart = (uint32_t)(wn * 8 + (q >> 1));   // 16B-unit base (+ jj*2)

    uint32_t stg[NSTAGE] = { sb, sb + STAGE_BYTES, sb + 2 * STAGE_BYTES };

    // prologue: chunks 0,1,2
    fillA(stg[0], W16);       fillB(stg[0], Xrow);                          CP_COMMIT();
    fillA(stg[1], W16 + 64);  fillB(stg[1], Xrow + (size_t)64  * NATOMS_);  CP_COMMIT();
    fillA(stg[2], W16 + 128); fillB(stg[2], Xrow + (size_t)128 * NATOMS_);  CP_COMMIT();

    float acc[2][8][4];
    #pragma unroll
    for (int i = 0; i < 2; i++)
        #pragma unroll
        for (int j = 0; j < 8; j++)
            #pragma unroll
            for (int e = 0; e < 4; e++) acc[i][j][e] = 0.0f;

    #pragma unroll 1
    for (int lc = 0; lc < 8; lc++) {
        if (lc < 6) CP_WAIT2(); else if (lc == 6) CP_WAIT1(); else CP_WAIT0();
        __syncthreads();                     // chunk lc visible block-wide

        int s = lc % 3;
        uint32_t aB = stg[s] + A_OFF;
        uint32_t bB = stg[s] + B_OFFS;

        #pragma unroll
        for (int ks = 0; ks < 4; ks++) {
            uint32_t kOff = (uint32_t)(ks * 32);
            uint32_t a4[8], b4[16];
            #pragma unroll
            for (int i = 0; i < 2; i++)
                ldsm_x4(&a4[i * 4], aB + sw128(aRow + i * 2048 + kOff + aCol));
            uint32_t kRow = (uint32_t)(ks * 16) + bKpart;
            #pragma unroll
            for (int jj = 0; jj < 4; jj++) {
                uint32_t un = bUpart + jj * 2;
                ldsm_x4t(&b4[jj * 4], bB + kRow * 256 + ((un * 16) ^ ((kRow & 7) * 16)));
            }
            #pragma unroll
            for (int i = 0; i < 2; i++)
                #pragma unroll
                for (int j = 0; j < 8; j++)
                    mma_f16(acc[i][j], &a4[i * 4], &b4[j * 2]);
        }

        if (lc < 5) {
            __syncthreads();                 // WAR: all consumed stage lc%3
            int f0 = (lc + 3) * 64;
            fillA(stg[s], W16 + f0);
            fillB(stg[s], Xrow + (size_t)f0 * NATOMS_);
            CP_COMMIT();
        }
    }

    // ---- epilogue: partial logits over this k-half ----
    float p[8][2];
    #pragma unroll
    for (int j = 0; j < 8; j++) { p[j][0] = 0.f; p[j][1] = 0.f; }

    int m0r = wm * 32 + (lane >> 2);
    #pragma unroll
    for (int i = 0; i < 2; i++) {
        float w0 = whg[m0r + i * 16];
        float w1 = whg[m0r + i * 16 + 8];
        #pragma unroll
        for (int j = 0; j < 8; j++) {
            p[j][0] = fmaf(w0, htanh(acc[i][j][0]), p[j][0]);
            p[j][1] = fmaf(w0, htanh(acc[i][j][1]), p[j][1]);
            p[j][0] = fmaf(w1, htanh(acc[i][j][2]), p[j][0]);
            p[j][1] = fmaf(w1, htanh(acc[i][j][3]), p[j][1]);
        }
    }
    #pragma unroll
    for (int off = 4; off <= 16; off <<= 1)
        #pragma unroll
        for (int j = 0; j < 8; j++) {
            p[j][0] += __shfl_xor_sync(0xffffffffu, p[j][0], off);
            p[j][1] += __shfl_xor_sync(0xffffffffu, p[j][1], off);
        }
    if (lane < 4) {
        #pragma unroll
        for (int j = 0; j < 8; j++) {
            int col = wn * 64 + j * 8 + lane * 2;
            part[wm * 128 + col]     = p[j][0];
            part[wm * 128 + col + 1] = p[j][1];
        }
    }
    __syncthreads();

    if (tid < 128) {
        float s = part[tid] + part[128 + tid] + part[256 + tid] + part[384 + tid];
        g_spart[unit][khalf][tid] = s;
    }
}

// ---------------- K2b: combine halves, softmax, alpha + vector outputs ----------------
// Reverse unit order: first-scheduled finish CTAs hit gemm's last (L2-hot) units.
__global__ void __launch_bounds__(512)
finish_kernel(float* __restrict__ out)
{
    __shared__ __align__(16) float alpha[NATOMS_];

    int tid  = threadIdx.x;
    int wid  = tid >> 5;
    int lane = tid & 31;

    int u   = (NUNITS - 1) - blockIdx.x;
    int src = u & 1;
    int b   = u >> 1;

    const __half* Xrow = g_X16[src] + (size_t)b * GFS_ * NATOMS_;

    // every warp redundantly reduces all 128 logits (no cross-warp tree)
    {
        float s[4];
        #pragma unroll
        for (int k = 0; k < 4; k++) {
            int n = lane + 32 * k;
            s[k] = g_spart[u][0][n] + g_spart[u][1][n];
        }
        float mx = fmaxf(fmaxf(s[0], s[1]), fmaxf(s[2], s[3]));
        #pragma unroll
        for (int off = 16; off; off >>= 1)
            mx = fmaxf(mx, __shfl_xor_sync(0xffffffffu, mx, off));
        float e[4], sum = 0.f;
        #pragma unroll
        for (int k = 0; k < 4; k++) { e[k] = __expf(s[k] - mx); sum += e[k]; }
        #pragma unroll
        for (int off = 16; off; off >>= 1)
            sum += __shfl_xor_sync(0xffffffffu, sum, off);
        float rs = 1.0f / sum;
        if (wid == 0) {
            #pragma unroll
            for (int k = 0; k < 4; k++) {
                int n = lane + 32 * k;
                float a = e[k] * rs;
                alpha[n] = a;
                out[2 * B_ * GFS_ + src * B_ * NATOMS_ + b * NATOMS_ + n] = a;
            }
        }
    }
    __syncthreads();

    // vector[f] = sum_n alpha[n] * X16[f][n], 1 f per thread (512 threads)
    {
        int f = tid;
        const uint4* xr = (const uint4*)(Xrow + (size_t)f * NATOMS_);
        float a = 0.0f;
        #pragma unroll
        for (int i = 0; i < 16; i++) {
            uint4 uu = xr[i];
            const float* al = alpha + i * 8;
            float2 p0 = __half22float2(*(const __half2*)&uu.x);
            float2 p1 = __half22float2(*(const __half2*)&uu.y);
            float2 p2 = __half22float2(*(const __half2*)&uu.z);
            float2 p3 = __half22float2(*(const __half2*)&uu.w);
            a = fmaf(p0.x, al[0], a); a = fmaf(p0.y, al[1], a);
            a = fmaf(p1.x, al[2], a); a = fmaf(p1.y, al[3], a);
            a = fmaf(p2.x, al[4], a); a = fmaf(p2.y, al[5], a);
            a = fmaf(p3.x, al[6], a); a = fmaf(p3.y, al[7], a);
        }
        out[src * B_ * GFS_ + b * GFS_ + f] = a;
    }
}

// ---------------- launch ----------------
extern "C" void kernel_launch(void* const* d_in, const int* in_sizes, int n_in,
                              void* d_out, int out_size)
{
    const float* V  = (const float*)d_in[0];
    const float* Q  = (const float*)d_in[1];
    const float* Wm = (const float*)d_in[2];
    const float* Wv = (const float*)d_in[3];
    const float* Wq = (const float*)d_in[4];
    const float* Wh = (const float*)d_in[5];
    float* out = (float*)d_out;

    cudaFuncSetAttribute(gemm_kernel, cudaFuncAttributeMaxDynamicSharedMemorySize, SMEM_K2A);

    m0_kernel<<<B_ * 4 + 256, 256>>>(V, Q, Wv, Wq);   // m0 + folded W prep
    gate_kernel<<<B_ / 4, 256>>>(Wm);
    gemm_kernel<<<NUNITS * 2, 256, SMEM_K2A>>>(Wh);
    finish_kernel<<<NUNITS, 512>>>(out);
}

// round 17
// speedup vs baseline: 1.1475x; 1.0217x over previous
#include <cuda_runtime.h>
#include <cuda_bf16.h>
#include <cuda_fp16.h>
#include <cstdint>

#define B_      512
#define GFS_    512
#define NATOMS_ 128
#define KATT_   256
#define NUNITS  (B_ * 2)

// ---------------- scratch (no cudaMalloc allowed) ----------------
__device__ float g_mgate[B_ * KATT_];
__device__ float g_M0[B_ * GFS_];
__device__ float g_spart[NUNITS][2][NATOMS_];                // partial logits per k-half
__device__ __half g_w16[2][KATT_ * GFS_];                    // W fp16
__device__ __half g_X16[2][(size_t)B_ * GFS_ * NATOMS_];     // X fp16, [b][f][n]

// ---------------- helpers ----------------
__device__ __forceinline__ uint32_t smem_u32(const void* p) {
    uint32_t a;
    asm("{ .reg .u64 t; cvta.to.shared.u64 t, %1; cvt.u32.u64 %0, t; }" : "=r"(a) : "l"(p));
    return a;
}
__device__ __forceinline__ uint32_t sw128(uint32_t off) { return off ^ ((off >> 3) & 0x70); }

__device__ __forceinline__ void ldsm_x4(uint32_t* r, uint32_t addr) {
    asm volatile("ldmatrix.sync.aligned.m8n8.x4.shared.b16 {%0,%1,%2,%3}, [%4];"
                 : "=r"(r[0]), "=r"(r[1]), "=r"(r[2]), "=r"(r[3]) : "r"(addr));
}
__device__ __forceinline__ void ldsm_x4t(uint32_t* r, uint32_t addr) {
    asm volatile("ldmatrix.sync.aligned.m8n8.x4.trans.shared.b16 {%0,%1,%2,%3}, [%4];"
                 : "=r"(r[0]), "=r"(r[1]), "=r"(r[2]), "=r"(r[3]) : "r"(addr));
}
__device__ __forceinline__ void mma_f16(float* c, const uint32_t* a, const uint32_t* b) {
    asm volatile("mma.sync.aligned.m16n8k16.row.col.f32.f16.f16.f32 "
                 "{%0,%1,%2,%3}, {%4,%5,%6,%7}, {%8,%9}, {%0,%1,%2,%3};"
                 : "+f"(c[0]), "+f"(c[1]), "+f"(c[2]), "+f"(c[3])
                 : "r"(a[0]), "r"(a[1]), "r"(a[2]), "r"(a[3]), "r"(b[0]), "r"(b[1]));
}
__device__ __forceinline__ void cp16(uint32_t saddr, const void* gaddr) {
    asm volatile("cp.async.cg.shared.global [%0], [%1], 16;" :: "r"(saddr), "l"(gaddr));
}
#define CP_COMMIT() asm volatile("cp.async.commit_group;" ::: "memory")
#define CP_WAIT0()  asm volatile("cp.async.wait_group 0;" ::: "memory")
#define CP_WAIT1()  asm volatile("cp.async.wait_group 1;" ::: "memory")
#define CP_WAIT2()  asm volatile("cp.async.wait_group 2;" ::: "memory")

// HW tanh (MUFU), rel err ~2^-11
__device__ __forceinline__ float htanh(float x) {
    float y;
    asm("tanh.approx.f32 %0, %1;" : "=f"(y) : "f"(x));
    return y;
}

// ---------------- precise rational tanh (gate path; |err| ~1e-7) ----------------
__device__ __forceinline__ float rtanh(float x) {
    float xc = fminf(fmaxf(x, -7.9053111f), 7.9053111f);
    float s = xc * xc;
    float p = -2.76076847742355e-16f;
    p = fmaf(p, s,  2.00018790482477e-13f);
    p = fmaf(p, s, -8.60467152213735e-11f);
    p = fmaf(p, s,  5.12229709037114e-08f);
    p = fmaf(p, s,  1.48572235717979e-05f);
    p = fmaf(p, s,  6.37261928875436e-04f);
    p = fmaf(p, s,  4.89352455891786e-03f);
    p = p * xc;
    float q = 1.19825839466702e-06f;
    q = fmaf(q, s, 1.18534705686654e-04f);
    q = fmaf(q, s, 2.26843463243900e-03f);
    q = fmaf(q, s, 4.89352518554385e-03f);
    return __fdividef(p, q);
}

// ---------------- K1a: rowsums -> M0 + X fp16 copy + (folded) W -> fp16 ----------------
// blocks [0, 2048): m0/X16 work. blocks [2048, 2304): W conversion.
__global__ __launch_bounds__(256) void m0_kernel(const float* __restrict__ V,
                                                 const float* __restrict__ Q,
                                                 const float* __restrict__ Wv,
                                                 const float* __restrict__ Wq)
{
    if (blockIdx.x >= 2048) {
        int id  = (blockIdx.x - 2048) * 256 + threadIdx.x;   // 0..65535
        int src = id >> 15;
        int e   = (id & 32767) * 4;
        const float* W = src ? Wq : Wv;
        float4 w = *(const float4*)(W + e);
        __half2 h0 = __floats2half2_rn(w.x, w.y);
        __half2 h1 = __floats2half2_rn(w.z, w.w);
        uint2 u = { *(uint32_t*)&h0, *(uint32_t*)&h1 };
        *(uint2*)(&g_w16[src][e]) = u;
        return;
    }

    int b    = blockIdx.x >> 2;
    int part = blockIdx.x & 3;
    int lane = threadIdx.x & 31;
    int warp = threadIdx.x >> 5;

    #pragma unroll
    for (int g = 0; g < 4; g++) {
        int f0 = part * 128 + warp * 16 + g * 4;
        size_t base = ((size_t)b * GFS_ + f0) * NATOMS_ + lane * 4;

        float4 v[4], q[4];
        #pragma unroll
        for (int j = 0; j < 4; j++) {
            v[j] = __ldcs((const float4*)(V + base + (size_t)j * NATOMS_));
            q[j] = __ldcs((const float4*)(Q + base + (size_t)j * NATOMS_));
        }

        #pragma unroll
        for (int j = 0; j < 4; j++) {
            __half2 vh0 = __floats2half2_rn(v[j].x, v[j].y);
            __half2 vh1 = __floats2half2_rn(v[j].z, v[j].w);
            __half2 qh0 = __floats2half2_rn(q[j].x, q[j].y);
            __half2 qh1 = __floats2half2_rn(q[j].z, q[j].w);
            uint2 vu = { *(uint32_t*)&vh0, *(uint32_t*)&vh1 };
            uint2 qu = { *(uint32_t*)&qh0, *(uint32_t*)&qh1 };
            __stcs((uint2*)(&g_X16[0][base + (size_t)j * NATOMS_]), vu);
            __stcs((uint2*)(&g_X16[1][base + (size_t)j * NATOMS_]), qu);
        }

        #pragma unroll
        for (int j = 0; j < 4; j++) {
            float sv = v[j].x + v[j].y + v[j].z + v[j].w;
            float sq = q[j].x + q[j].y + q[j].z + q[j].w;
            #pragma unroll
            for (int off = 16; off; off >>= 1) {
                sv += __shfl_xor_sync(0xffffffffu, sv, off);
                sq += __shfl_xor_sync(0xffffffffu, sq, off);
            }
            if (lane == 0)
                g_M0[b * GFS_ + f0 + j] = rtanh(sv * (1.0f / 64.0f)) * rtanh(sq * (1.0f / 64.0f));
        }
    }
}

// ---------------- K1b: m_gate = tanh(Wm @ M0), 4 batches per CTA ----------------
__global__ __launch_bounds__(256) void gate_kernel(const float* __restrict__ Wm)
{
    __shared__ __align__(16) float M0s[4][GFS_];
    int b0  = blockIdx.x * 4;
    int tid = threadIdx.x;

    for (int i = tid; i < 4 * GFS_ / 4; i += 256)
        ((float4*)&M0s[0][0])[i] = ((const float4*)(g_M0 + b0 * GFS_))[i];
    __syncthreads();

    int k = tid;
    const float4* wr = (const float4*)(Wm + (size_t)k * GFS_);
    float acc0 = 0.f, acc1 = 0.f, acc2 = 0.f, acc3 = 0.f;
    #pragma unroll 4
    for (int i = 0; i < GFS_ / 4; i++) {
        float4 w = wr[i];
        float4 m0 = ((const float4*)M0s[0])[i];
        float4 m1 = ((const float4*)M0s[1])[i];
        float4 m2 = ((const float4*)M0s[2])[i];
        float4 m3 = ((const float4*)M0s[3])[i];
        acc0 = fmaf(w.x, m0.x, fmaf(w.y, m0.y, fmaf(w.z, m0.z, fmaf(w.w, m0.w, acc0))));
        acc1 = fmaf(w.x, m1.x, fmaf(w.y, m1.y, fmaf(w.z, m1.z, fmaf(w.w, m1.w, acc1))));
        acc2 = fmaf(w.x, m2.x, fmaf(w.y, m2.y, fmaf(w.z, m2.z, fmaf(w.w, m2.w, acc2))));
        acc3 = fmaf(w.x, m3.x, fmaf(w.y, m3.y, fmaf(w.z, m3.z, fmaf(w.w, m3.w, acc3))));
    }
    g_mgate[(b0 + 0) * KATT_ + k] = rtanh(acc0);
    g_mgate[(b0 + 1) * KATT_ + k] = rtanh(acc1);
    g_mgate[(b0 + 2) * KATT_ + k] = rtanh(acc2);
    g_mgate[(b0 + 3) * KATT_ + k] = rtanh(acc3);
}

// ---------------- K2a: split-K GEMM + tanh-reduce, 2 CTAs/SM (R12-verified) ----------------
#define A_OFF       0
#define B_OFFS      16384
#define STAGE_BYTES 32768
#define NSTAGE      3
#define WHG_OFF     98304
#define PART_OFF    98816
#define SMEM_K2A    100864

// A chunk [128 m][64 f] fp16 SW128 (rows 128B)
__device__ __forceinline__ void fillA(uint32_t stage, const __half* Wc)
{
    int tid = threadIdx.x;
    #pragma unroll
    for (int it = 0; it < 4; it++) {
        int idx = it * 256 + tid;          // 0..1023
        int m   = idx >> 3;
        int u   = idx & 7;
        cp16(stage + A_OFF + sw128((uint32_t)(m * 128 + u * 16)),
             Wc + (size_t)m * GFS_ + u * 8);
    }
}

// B chunk [64 k(f)][128 n] fp16, rows 256B, 16B-unit XOR by (k&7)
__device__ __forceinline__ void fillB(uint32_t stage, const __half* Xc)
{
    int tid = threadIdx.x;
    #pragma unroll
    for (int it = 0; it < 4; it++) {
        int idx = it * 256 + tid;          // 0..1023
        int k   = idx >> 4;
        int u   = idx & 15;
        cp16(stage + B_OFFS + (uint32_t)(k * 256 + ((u << 4) ^ ((k & 7) << 4))),
             Xc + (size_t)k * NATOMS_ + u * 8);
    }
}

__global__ void __launch_bounds__(256, 2)
gemm_kernel(const float* __restrict__ Wh)
{
    extern __shared__ char sm[];
    uint32_t sb = smem_u32(sm);

    int tid  = threadIdx.x;
    int wid  = tid >> 5;        // 0..7
    int lane = tid & 31;

    int unit  = blockIdx.x >> 1;
    int khalf = blockIdx.x & 1;
    int src   = unit & 1;
    int b     = unit >> 1;

    const __half* W16  = g_w16[src] + (size_t)khalf * 128 * GFS_;
    const __half* Xrow = g_X16[src] + (size_t)b * GFS_ * NATOMS_;

    float* whg  = (float*)(sm + WHG_OFF);    // 128 gated weights for this k-half
    float* part = (float*)(sm + PART_OFF);   // 4 x 128

    if (tid < 128) {
        int k = khalf * 128 + tid;
        whg[tid] = Wh[k] * g_mgate[b * KATT_ + k];
    }

    // warp tile: 32m x 64n; warp grid 4(m) x 2(n)
    int wm = wid >> 1;
    int wn = wid & 1;

    uint32_t aRow = (uint32_t)((wm * 32 + (lane & 15)) * 128);
    uint32_t aCol = (uint32_t)((lane >> 4) * 16);
    int q = lane >> 3;
    int r = lane & 7;
    uint32_t bKpart = (uint32_t)((q & 1) * 8 + r);
    uint32_t bUpart = (uint32_t)(wn * 8 + (q >> 1));   // 16B-unit base (+ jj*2)

    uint32_t stg[NSTAGE] = { sb, sb + STAGE_BYTES, sb + 2 * STAGE_BYTES };

    // prologue: chunks 0,1,2
    fillA(stg[0], W16);       fillB(stg[0], Xrow);                          CP_COMMIT();
    fillA(stg[1], W16 + 64);  fillB(stg[1], Xrow + (size_t)64  * NATOMS_);  CP_COMMIT();
    fillA(stg[2], W16 + 128); fillB(stg[2], Xrow + (size_t)128 * NATOMS_);  CP_COMMIT();

    float acc[2][8][4];
    #pragma unroll
    for (int i = 0; i < 2; i++)
        #pragma unroll
        for (int j = 0; j < 8; j++)
            #pragma unroll
            for (int e = 0; e < 4; e++) acc[i][j][e] = 0.0f;

    #pragma unroll 1
    for (int lc = 0; lc < 8; lc++) {
        if (lc < 6) CP_WAIT2(); else if (lc == 6) CP_WAIT1(); else CP_WAIT0();
        __syncthreads();                     // chunk lc visible block-wide

        int s = lc % 3;
        uint32_t aB = stg[s] + A_OFF;
        uint32_t bB = stg[s] + B_OFFS;

        #pragma unroll
        for (int ks = 0; ks < 4; ks++) {
            uint32_t kOff = (uint32_t)(ks * 32);
            uint32_t a4[8], b4[16];
            #pragma unroll
            for (int i = 0; i < 2; i++)
                ldsm_x4(&a4[i * 4], aB + sw128(aRow + i * 2048 + kOff + aCol));
            uint32_t kRow = (uint32_t)(ks * 16) + bKpart;
            #pragma unroll
            for (int jj = 0; jj < 4; jj++) {
                uint32_t un = bUpart + jj * 2;
                ldsm_x4t(&b4[jj * 4], bB + kRow * 256 + ((un * 16) ^ ((kRow & 7) * 16)));
            }
            #pragma unroll
            for (int i = 0; i < 2; i++)
                #pragma unroll
                for (int j = 0; j < 8; j++)
                    mma_f16(acc[i][j], &a4[i * 4], &b4[j * 2]);
        }

        if (lc < 5) {
            __syncthreads();                 // WAR: all consumed stage lc%3
            int f0 = (lc + 3) * 64;
            fillA(stg[s], W16 + f0);
            fillB(stg[s], Xrow + (size_t)f0 * NATOMS_);
            CP_COMMIT();
        }
    }

    // ---- epilogue: partial logits over this k-half ----
    float p[8][2];
    #pragma unroll
    for (int j = 0; j < 8; j++) { p[j][0] = 0.f; p[j][1] = 0.f; }

    int m0r = wm * 32 + (lane >> 2);
    #pragma unroll
    for (int i = 0; i < 2; i++) {
        float w0 = whg[m0r + i * 16];
        float w1 = whg[m0r + i * 16 + 8];
        #pragma unroll
        for (int j = 0; j < 8; j++) {
            p[j][0] = fmaf(w0, htanh(acc[i][j][0]), p[j][0]);
            p[j][1] = fmaf(w0, htanh(acc[i][j][1]), p[j][1]);
            p[j][0] = fmaf(w1, htanh(acc[i][j][2]), p[j][0]);
            p[j][1] = fmaf(w1, htanh(acc[i][j][3]), p[j][1]);
        }
    }
    #pragma unroll
    for (int off = 4; off <= 16; off <<= 1)
        #pragma unroll
        for (int j = 0; j < 8; j++) {
            p[j][0] += __shfl_xor_sync(0xffffffffu, p[j][0], off);
            p[j][1] += __shfl_xor_sync(0xffffffffu, p[j][1], off);
        }
    if (lane < 4) {
        #pragma unroll
        for (int j = 0; j < 8; j++) {
            int col = wn * 64 + j * 8 + lane * 2;
            part[wm * 128 + col]     = p[j][0];
            part[wm * 128 + col + 1] = p[j][1];
        }
    }
    __syncthreads();

    if (tid < 128) {
        float s = part[tid] + part[128 + tid] + part[256 + tid] + part[384 + tid];
        g_spart[unit][khalf][tid] = s;
    }
}

// ---------------- K2b: combine halves, softmax, alpha + vector outputs ----------------
// Reverse unit order (L2 reuse); vectorized alpha (float4 LDS) + batched X loads.
__global__ void __launch_bounds__(512)
finish_kernel(float* __restrict__ out)
{
    __shared__ __align__(16) float alpha[NATOMS_];

    int tid  = threadIdx.x;
    int wid  = tid >> 5;
    int lane = tid & 31;

    int u   = (NUNITS - 1) - blockIdx.x;
    int src = u & 1;
    int b   = u >> 1;

    const __half* Xrow = g_X16[src] + (size_t)b * GFS_ * NATOMS_;

    // every warp redundantly reduces all 128 logits (no cross-warp tree)
    {
        float s[4];
        #pragma unroll
        for (int k = 0; k < 4; k++) {
            int n = lane + 32 * k;
            s[k] = g_spart[u][0][n] + g_spart[u][1][n];
        }
        float mx = fmaxf(fmaxf(s[0], s[1]), fmaxf(s[2], s[3]));
        #pragma unroll
        for (int off = 16; off; off >>= 1)
            mx = fmaxf(mx, __shfl_xor_sync(0xffffffffu, mx, off));
        float e[4], sum = 0.f;
        #pragma unroll
        for (int k = 0; k < 4; k++) { e[k] = __expf(s[k] - mx); sum += e[k]; }
        #pragma unroll
        for (int off = 16; off; off >>= 1)
            sum += __shfl_xor_sync(0xffffffffu, sum, off);
        float rs = 1.0f / sum;
        if (wid == 0) {
            #pragma unroll
            for (int k = 0; k < 4; k++) {
                int n = lane + 32 * k;
                float a = e[k] * rs;
                alpha[n] = a;
                out[2 * B_ * GFS_ + src * B_ * NATOMS_ + b * NATOMS_ + n] = a;
            }
        }
    }
    __syncthreads();

    // vector[f] = sum_n alpha[n] * X16[f][n], 1 f per thread.
    // alpha via float4 LDS (32 instead of 128 scalar LDS); X in batched pairs.
    {
        int f = tid;
        const uint4*  xr  = (const uint4*)(Xrow + (size_t)f * NATOMS_);
        const float4* al4 = (const float4*)alpha;
        float a0 = 0.0f, a1 = 0.0f;
        #pragma unroll
        for (int i = 0; i < 16; i += 2) {
            uint4 x0 = __ldcs(xr + i);
            uint4 x1 = __ldcs(xr + i + 1);
            float4 aA = al4[2 * i + 0];
            float4 aB = al4[2 * i + 1];
            float4 aC = al4[2 * i + 2];
            float4 aD = al4[2 * i + 3];
            float2 p0 = __half22float2(*(const __half2*)&x0.x);
            float2 p1 = __half22float2(*(const __half2*)&x0.y);
            float2 p2 = __half22float2(*(const __half2*)&x0.z);
            float2 p3 = __half22float2(*(const __half2*)&x0.w);
            a0 = fmaf(p0.x, aA.x, a0); a0 = fmaf(p0.y, aA.y, a0);
            a0 = fmaf(p1.x, aA.z, a0); a0 = fmaf(p1.y, aA.w, a0);
            a0 = fmaf(p2.x, aB.x, a0); a0 = fmaf(p2.y, aB.y, a0);
            a0 = fmaf(p3.x, aB.z, a0); a0 = fmaf(p3.y, aB.w, a0);
            float2 q0 = __half22float2(*(const __half2*)&x1.x);
            float2 q1 = __half22float2(*(const __half2*)&x1.y);
            float2 q2 = __half22float2(*(const __half2*)&x1.z);
            float2 q3 = __half22float2(*(const __half2*)&x1.w);
            a1 = fmaf(q0.x, aC.x, a1); a1 = fmaf(q0.y, aC.y, a1);
            a1 = fmaf(q1.x, aC.z, a1); a1 = fmaf(q1.y, aC.w, a1);
            a1 = fmaf(q2.x, aD.x, a1); a1 = fmaf(q2.y, aD.y, a1);
            a1 = fmaf(q3.x, aD.z, a1); a1 = fmaf(q3.y, aD.w, a1);
        }
        out[src * B_ * GFS_ + b * GFS_ + f] = a0 + a1;
    }
}

// ---------------- launch ----------------
extern "C" void kernel_launch(void* const* d_in, const int* in_sizes, int n_in,
                              void* d_out, int out_size)
{
    const float* V  = (const float*)d_in[0];
    const float* Q  = (const float*)d_in[1];
    const float* Wm = (const float*)d_in[2];
    const float* Wv = (const float*)d_in[3];
    const float* Wq = (const float*)d_in[4];
    const float* Wh = (const float*)d_in[5];
    float* out = (float*)d_out;

    cudaFuncSetAttribute(gemm_kernel, cudaFuncAttributeMaxDynamicSharedMemorySize, SMEM_K2A);

    m0_kernel<<<B_ * 4 + 256, 256>>>(V, Q, Wv, Wq);   // m0 + folded W prep
    gate_kernel<<<B_ / 4, 256>>>(Wm);
    gemm_kernel<<<NUNITS * 2, 256, SMEM_K2A>>>(Wh);
    finish_kernel<<<NUNITS, 512>>>(out);
}